// round 13
// baseline (speedup 1.0000x reference)
#include <cuda_runtime.h>
#include <cuda_bf16.h>
#include <math.h>
#include <stdint.h>

// ---------------- problem constants ----------------
#define BATCH   2
#define TT      4096
#define BT      8192
#define NQ      256
#define NAUX    28
#define NR      512
#define NS      256
#define NLAYERS 30

// ---------------- main GEMM tiling ----------------
#define BM 128
#define BN 128
#define NTHREADS 288          // 8 consumer warps + 1 producer warp
#define NSTAGES 3

// smem strides (elements)
#define SA 40
#define SB 136

// ---------------- device scratch ----------------
__device__ float d_res [NR * BT];
__device__ float d_o1  [NS * BT];
__device__ float d_skip[NS * BT];

__device__ __nv_bfloat16 d_resH[NR * BT], d_resL[NR * BT];
__device__ __nv_bfloat16 d_s1H [NR * BT], d_s1L [NR * BT];
__device__ __nv_bfloat16 d_gH  [NR * BT], d_gL  [NR * BT];
__device__ __nv_bfloat16 d_hH  [32 * BT], d_hL  [32 * BT];

__device__ __nv_bfloat16 d_WgH [NLAYERS * 2 * 1024 * 512], d_WgL [NLAYERS * 2 * 1024 * 512];
__device__ __nv_bfloat16 d_WaH [NLAYERS * 1024 * 32],      d_WaL [NLAYERS * 1024 * 32];
__device__ __nv_bfloat16 d_WrsH[NLAYERS * 768 * 512],      d_WrsL[NLAYERS * 768 * 512];

__device__ float d_bg [NLAYERS * 1024];
__device__ float d_brs[NLAYERS * 768];

__device__ uint2 d_Wp12[128 * 256];
__device__ uint2 d_Wp22[128 * 256];
__device__ uint2 d_Wp32[128 * 256];

// ---------------- helpers ----------------
__device__ __forceinline__ uint32_t pk2(__nv_bfloat16 a, __nv_bfloat16 b) {
    return (uint32_t)__bfloat16_as_ushort(a) | ((uint32_t)__bfloat16_as_ushort(b) << 16);
}

__device__ __forceinline__ uint2 split2(float x, float y) {
    __nv_bfloat16 xh = __float2bfloat16_rn(x);
    __nv_bfloat16 yh = __float2bfloat16_rn(y);
    __nv_bfloat16 xl = __float2bfloat16_rn(x - __bfloat162float(xh));
    __nv_bfloat16 yl = __float2bfloat16_rn(y - __bfloat162float(yh));
    uint2 w; w.x = pk2(xh, yh); w.y = pk2(xl, yl); return w;
}

__device__ __forceinline__ void splitHL(float v, __nv_bfloat16* H, __nv_bfloat16* L, size_t o) {
    __nv_bfloat16 hh = __float2bfloat16_rn(v);
    H[o] = hh; L[o] = __float2bfloat16_rn(v - __bfloat162float(hh));
}

__device__ __forceinline__ void mma16(float* c, const uint32_t* a, const uint32_t* b) {
    asm volatile(
        "mma.sync.aligned.m16n8k16.row.col.f32.bf16.bf16.f32 "
        "{%0,%1,%2,%3}, {%4,%5,%6,%7}, {%8,%9}, {%0,%1,%2,%3};\n"
        : "+f"(c[0]), "+f"(c[1]), "+f"(c[2]), "+f"(c[3])
        : "r"(a[0]), "r"(a[1]), "r"(a[2]), "r"(a[3]), "r"(b[0]), "r"(b[1]));
}

__device__ __forceinline__ void ldm_x4(uint32_t* r, uint32_t saddr) {
    asm volatile("ldmatrix.sync.aligned.m8n8.x4.shared.b16 {%0,%1,%2,%3}, [%4];"
        : "=r"(r[0]), "=r"(r[1]), "=r"(r[2]), "=r"(r[3]) : "r"(saddr));
}
__device__ __forceinline__ void ldm_x4t(uint32_t* r, uint32_t saddr) {
    asm volatile("ldmatrix.sync.aligned.m8n8.x4.trans.shared.b16 {%0,%1,%2,%3}, [%4];"
        : "=r"(r[0]), "=r"(r[1]), "=r"(r[2]), "=r"(r[3]) : "r"(saddr));
}

__device__ __forceinline__ void cp16(void* dst, const void* src) {
    uint32_t s = (uint32_t)__cvta_generic_to_shared(dst);
    asm volatile("cp.async.cg.shared.global [%0], [%1], 16;\n" :: "r"(s), "l"(src));
}
__device__ __forceinline__ void cp16z(void* dst, const void* src, int valid) {
    uint32_t s = (uint32_t)__cvta_generic_to_shared(dst);
    asm volatile("cp.async.cg.shared.global [%0], [%1], 16, %2;\n"
                 :: "r"(s), "l"(src), "r"(valid ? 16 : 0));
}

// ---- mbarrier helpers ----
__device__ __forceinline__ void mbar_init(uint32_t m, uint32_t cnt) {
    asm volatile("mbarrier.init.shared.b64 [%0], %1;" :: "r"(m), "r"(cnt) : "memory");
}
__device__ __forceinline__ void mbar_arrive(uint32_t m) {
    asm volatile("mbarrier.arrive.shared.b64 _, [%0];" :: "r"(m) : "memory");
}
// NOTE: .noinc is load-bearing. Without it the arrive first increments the
// pending count (net zero) and the barrier phase never completes -> deadlock.
__device__ __forceinline__ void cpasync_mbar_arrive(uint32_t m) {
    asm volatile("cp.async.mbarrier.arrive.noinc.shared.b64 [%0];" :: "r"(m) : "memory");
}
__device__ __forceinline__ void mbar_wait(uint32_t m, uint32_t parity) {
    asm volatile(
        "{\n\t.reg .pred P;\n"
        "W%=:\n\tmbarrier.try_wait.parity.acquire.cta.shared::cta.b64 P, [%0], %1, 0x989680;\n"
        "\t@P bra D%=;\n\tbra W%=;\nD%=:\n\t}"
        :: "r"(m), "r"(parity) : "memory");
}

__device__ __forceinline__ int gate_channel_of_row(int mlocal) {
    return ((mlocal >> 4) << 3) | (mlocal & 7);
}
__device__ __forceinline__ int gate_c_of_m(int m) {
    int mlocal = m & 127;
    int cc = gate_channel_of_row(mlocal & ~8);
    return (m >> 7) * 64 + cc;
}
__device__ __forceinline__ int gate_half_of_m(int m) { return (m >> 3) & 1; }

struct Stage {
    __nv_bfloat16 AH[128][SA];
    __nv_bfloat16 AL[128][SA];
    __nv_bfloat16 BH[32][SB];
    __nv_bfloat16 BL[32][SB];
};
static_assert(sizeof(Stage) == 37888, "stage size");
#define MBAR_OFF  (NSTAGES * (int)sizeof(Stage))       // 113664
#define GEMM_SMEM (MBAR_OFF + 64)                      // 113728

// =====================================================================
// Consumer compute over one stage
// =====================================================================
#define COMPUTE_TILE(S_, stage_, acc_)                                          \
    do {                                                                        \
        uint32_t aH_ = (uint32_t)__cvta_generic_to_shared(&(S_)[stage_].AH[0][0]); \
        uint32_t aL_ = (uint32_t)__cvta_generic_to_shared(&(S_)[stage_].AL[0][0]); \
        uint32_t bH_ = (uint32_t)__cvta_generic_to_shared(&(S_)[stage_].BH[0][0]); \
        uint32_t bL_ = (uint32_t)__cvta_generic_to_shared(&(S_)[stage_].BL[0][0]); \
        _Pragma("unroll")                                                       \
        for (int k16 = 0; k16 < 2; ++k16) {                                     \
            uint32_t bfH_[2][4], bfL_[2][4];                                    \
            _Pragma("unroll")                                                   \
            for (int hh = 0; hh < 2; ++hh) {                                    \
                uint32_t boff = (uint32_t)((k16 * 16 + rowB) * (SB * 2)         \
                                           + warp_n * 64 + hh * 32 + colBq);    \
                ldm_x4t(bfH_[hh], bH_ + boff);                                  \
                ldm_x4t(bfL_[hh], bL_ + boff);                                  \
            }                                                                   \
            _Pragma("unroll")                                                   \
            for (int mt = 0; mt < 4; ++mt) {                                    \
                uint32_t afH_[4], afL_[4];                                      \
                uint32_t off = (uint32_t)((warp_m * 64 + mt * 16 + rowA)        \
                                          * (SA * 2) + k16 * 32 + kbA);         \
                ldm_x4(afH_, aH_ + off);                                        \
                ldm_x4(afL_, aL_ + off);                                        \
                _Pragma("unroll")                                               \
                for (int nt = 0; nt < 4; ++nt)                                  \
                    mma16((acc_)[mt][nt], afH_, bfH_[nt >> 1] + (nt & 1) * 2);  \
                _Pragma("unroll")                                               \
                for (int nt = 0; nt < 4; ++nt)                                  \
                    mma16((acc_)[mt][nt], afH_, bfL_[nt >> 1] + (nt & 1) * 2);  \
                _Pragma("unroll")                                               \
                for (int nt = 0; nt < 4; ++nt)                                  \
                    mma16((acc_)[mt][nt], afL_, bfH_[nt >> 1] + (nt & 1) * 2);  \
            }                                                                   \
        }                                                                       \
    } while (0)

// =====================================================================
// Packing / init / embed
// =====================================================================
__global__ void pack_all_k(const float* __restrict__ dsw, const float* __restrict__ dtw,
                           const float* __restrict__ asw, const float* __restrict__ atw,
                           const float* __restrict__ skw, const float* __restrict__ rew,
                           const float* __restrict__ dsb, const float* __restrict__ dtb,
                           const float* __restrict__ asb, const float* __restrict__ atb,
                           const float* __restrict__ skb, const float* __restrict__ reb,
                           const float* __restrict__ p1w, const float* __restrict__ p2w,
                           const float* __restrict__ p3w, const float* __restrict__ h) {
    size_t gi = (size_t)blockIdx.x * blockDim.x + threadIdx.x;
    const size_t N1 = (size_t)NLAYERS * 2 * 1024 * 512;
    const size_t N2 = (size_t)NLAYERS * 1024 * 32;
    const size_t N3 = (size_t)NLAYERS * 768 * 512;
    const size_t N4 = (size_t)NLAYERS * (1024 + 768);
    const size_t N5 = 3 * 128 * 256;
    const size_t N6 = (size_t)32 * BT;

    if (gi < N1) {
        int idx = (int)gi;
        int k = idx & 511, rm = idx >> 9;
        int m = rm & 1023, lt = rm >> 10;
        int tap = lt & 1, l = lt >> 1, c = gate_c_of_m(m);
        const float* src = gate_half_of_m(m) ? dtw : dsw;
        splitHL(src[((size_t)(l * NR + c) * NR + k) * 2 + tap], d_WgH, d_WgL, idx);
        return;
    }
    gi -= N1;
    if (gi < N2) {
        int idx = (int)gi;
        int k = idx & 31, rm = idx >> 5;
        int m = rm & 1023, l = rm >> 10, c = gate_c_of_m(m);
        const float* src = gate_half_of_m(m) ? atw : asw;
        splitHL((k < NAUX) ? src[(size_t)(l * NR + c) * NAUX + k] : 0.f, d_WaH, d_WaL, idx);
        return;
    }
    gi -= N2;
    if (gi < N3) {
        int idx = (int)gi;
        int k = idx & 511, rm = idx >> 9;
        int m = rm % 768, l = rm / 768;
        float v = (m < 256) ? skw[(size_t)(l * NS + m) * NR + k]
                            : rew[(size_t)(l * NR + (m - 256)) * NR + k];
        splitHL(v, d_WrsH, d_WrsL, idx);
        return;
    }
    gi -= N3;
    if (gi < N4) {
        int idx = (int)gi;
        if (idx < NLAYERS * 1024) {
            int l = idx >> 10, m = idx & 1023, c = gate_c_of_m(m);
            d_bg[idx] = gate_half_of_m(m) ? (dtb[l * NR + c] + atb[l * NR + c])
                                          : (dsb[l * NR + c] + asb[l * NR + c]);
        } else {
            int j = idx - NLAYERS * 1024;
            int l = j / 768, m = j % 768;
            d_brs[j] = (m < 256) ? skb[l * NS + m] : reb[l * NR + (m - 256)];
        }
        return;
    }
    gi -= N4;
    if (gi < N5) {
        int idx = (int)gi;
        int w = idx / 32768, r = idx % 32768;
        int k2 = r >> 8, m = r & 255;
        const float* p = (w == 0) ? p1w : (w == 1) ? p2w : p3w;
        uint2 v = split2(p[m * 256 + 2 * k2], p[m * 256 + 2 * k2 + 1]);
        if (w == 0)      d_Wp12[r] = v;
        else if (w == 1) d_Wp22[r] = v;
        else             d_Wp32[r] = v;
        return;
    }
    gi -= N5;
    if (gi < N6) {
        int idx = (int)gi;
        int a = idx / BT, j = idx % BT;
        float v = 0.f;
        if (a < NAUX) {
            int b = j >> 12, t = j & (TT - 1);
            v = h[((size_t)b * NAUX + a) * TT + t];
        }
        splitHL(v, d_hH, d_hL, idx);
    }
}
#define PACK_TOTAL ((size_t)NLAYERS*2*1024*512 + (size_t)NLAYERS*1024*32 + \
                    (size_t)NLAYERS*768*512 + (size_t)NLAYERS*(1024+768) + \
                    3*128*256 + (size_t)32*BT)

__global__ void zero_skip_k() {
    int idx = blockIdx.x * blockDim.x + threadIdx.x;
    if (idx < NS * BT) d_skip[idx] = 0.f;
}

__global__ void embed_k(const int* __restrict__ x, const float* __restrict__ cw,
                        const float* __restrict__ cb) {
    int j = blockIdx.x * blockDim.x + threadIdx.x;
    int c = blockIdx.y;
    if (j >= BT) return;
    int b = j >> 12;
    int t = j & (TT - 1);
    int q1 = x[b * TT + t] & 255;
    float v = cw[(c * NQ + q1) * 2 + 1] + cb[c];
    if (t > 0) {
        int q0 = x[b * TT + t - 1] & 255;
        v += cw[(c * NQ + q0) * 2 + 0];
    }
    size_t o = (size_t)c * BT + j;
    d_res[o] = v;
    splitHL(v, d_resH, d_resL, o);
    if (t + 1 < TT) splitHL(v, d_s1H, d_s1L, o + 1);
    if (t == 0) {
        __nv_bfloat16 z = __float2bfloat16_rn(0.f);
        d_s1H[o] = z; d_s1L[o] = z;
    }
}

// =====================================================================
// Gate GEMM: producer/consumer mbarrier pipeline, no per-tile CTA barrier.
// =====================================================================
__global__ __launch_bounds__(NTHREADS, 2)
void gate_k(int l, int d, int useS1) {
    extern __shared__ uint8_t smraw[];
    Stage* S = reinterpret_cast<Stage*>(smraw);
    uint32_t mb_base = (uint32_t)__cvta_generic_to_shared(smraw + MBAR_OFF);

    int tid    = threadIdx.x;
    int lane   = tid & 31;
    int wid    = tid >> 5;          // 0..8
    int mb     = blockIdx.x;
    int t0     = blockIdx.y * BN;
    int z      = blockIdx.z;

    if (tid == 0) {
        #pragma unroll
        for (int s = 0; s < NSTAGES; ++s) {
            mbar_init(mb_base + s * 8, 32);                    // full: producer threads
            mbar_init(mb_base + 24 + s * 8, 8);                // empty: consumer warps
        }
    }
    __syncthreads();

    const int NT = 33;

    if (wid == 8) {
        // ---------------- producer warp ----------------
        int ps = 0; uint32_t pp = 1;
        for (int t = 0; t < NT; ++t) {
            mbar_wait(mb_base + 24 + ps * 8, pp);
            // fill A (1024 cp.async)
            {
                const __nv_bfloat16 *PH, *PL;
                int rowstride;
                if (t < 32) {
                    int tap = t >> 4;
                    int kt  = (t & 15) * 32;
                    size_t off = ((size_t)((l * 2 + tap) * 1024) + mb * 128) * 512 + kt;
                    PH = d_WgH + off; PL = d_WgL + off; rowstride = 512;
                } else {
                    size_t off = ((size_t)l * 1024 + mb * 128) * 32;
                    PH = d_WaH + off; PL = d_WaL + off; rowstride = 32;
                }
                #pragma unroll 8
                for (int q = 0; q < 32; ++q) {
                    int idx = q * 32 + lane;
                    int pl  = idx >> 9;
                    int rem = idx & 511;
                    int row = rem >> 2;
                    int kc  = rem & 3;
                    const __nv_bfloat16* src = (pl ? PL : PH) + (size_t)row * rowstride + kc * 8;
                    __nv_bfloat16* dst = pl ? &S[ps].AL[row][kc * 8] : &S[ps].AH[row][kc * 8];
                    cp16(dst, src);
                }
            }
            // fill B (1024 cp.async)
            {
                const __nv_bfloat16 *baseH, *baseL;
                int kt, doff;
                if (t < 16) {
                    baseH = useS1 ? d_s1H : d_resH;
                    baseL = useS1 ? d_s1L : d_resL;
                    kt = t * 32; doff = useS1 ? 0 : d;
                } else if (t < 32) {
                    baseH = d_resH; baseL = d_resL; kt = (t - 16) * 32; doff = 0;
                } else {
                    baseH = d_hH; baseL = d_hL; kt = 0; doff = 0;
                }
                #pragma unroll 8
                for (int q = 0; q < 32; ++q) {
                    int idx = q * 32 + lane;
                    int pl  = idx >> 9;
                    int rem = idx & 511;
                    int row = rem >> 4;
                    int c16 = rem & 15;
                    int col = t0 + c16 * 8 - doff;
                    const __nv_bfloat16* bp = pl ? baseL : baseH;
                    const __nv_bfloat16* src = bp + (size_t)(kt + row) * BT + (size_t)z * TT
                                                  + (col >= 0 ? col : 0);
                    __nv_bfloat16* dst = pl ? &S[ps].BL[row][c16 * 8] : &S[ps].BH[row][c16 * 8];
                    cp16z(dst, src, col >= 0);
                }
            }
            cpasync_mbar_arrive(mb_base + ps * 8);
            if (++ps == NSTAGES) { ps = 0; pp ^= 1; }
        }
        return;   // producer exits
    }

    // ---------------- consumer warps (wid 0..7) ----------------
    int warp_m = wid & 1;
    int warp_n = wid >> 1;
    int subA  = lane >> 3;
    int rowA  = (subA & 1) * 8 + (lane & 7);
    int kbA   = (subA >> 1) * 16;
    int rowB  = lane & 15;
    int colBq = (lane >> 4) * 16;

    float acc[4][4][4] = {};

    int cs = 0; uint32_t cp_ = 0;
    for (int t = 0; t < NT; ++t) {
        mbar_wait(mb_base + cs * 8, cp_);
        COMPUTE_TILE(S, cs, acc);
        __syncwarp();
        if (lane == 0) mbar_arrive(mb_base + 24 + cs * 8);
        if (++cs == NSTAGES) { cs = 0; cp_ ^= 1; }
    }

    // gated activation epilogue -> g planes
    const float* bgp = d_bg + l * 1024 + mb * 128;
    int colbase = z * TT + t0 + warp_n * 32 + (lane & 3) * 2;
    #pragma unroll
    for (int mt = 0; mt < 4; ++mt) {
        int r  = warp_m * 64 + mt * 16 + (lane >> 2);
        int cc = gate_channel_of_row(r);
        int cg = mb * 64 + cc;
        float bs = bgp[r];
        float bt = bgp[r + 8];
        #pragma unroll
        for (int nt = 0; nt < 4; ++nt) {
            float s0  = acc[mt][nt][0] + bs;
            float s1  = acc[mt][nt][1] + bs;
            float tv0 = acc[mt][nt][2] + bt;
            float tv1 = acc[mt][nt][3] + bt;
            float g0 = __fdividef(1.f, 1.f + __expf(-s0)) *
                       (1.f - __fdividef(2.f, __expf(2.f * tv0) + 1.f));
            float g1 = __fdividef(1.f, 1.f + __expf(-s1)) *
                       (1.f - __fdividef(2.f, __expf(2.f * tv1) + 1.f));
            uint2 w = split2(g0, g1);
            size_t o = (size_t)cg * BT + colbase + nt * 8;
            *(uint32_t*)&d_gH[o] = w.x;
            *(uint32_t*)&d_gL[o] = w.y;
        }
    }
}

// =====================================================================
// Skip/Res GEMM: same producer/consumer pipeline, M=768, K=512
// =====================================================================
__global__ __launch_bounds__(NTHREADS, 2)
void skipres_k(int l, int dnext) {
    extern __shared__ uint8_t smraw[];
    Stage* S = reinterpret_cast<Stage*>(smraw);
    uint32_t mb_base = (uint32_t)__cvta_generic_to_shared(smraw + MBAR_OFF);

    int tid    = threadIdx.x;
    int lane   = tid & 31;
    int wid    = tid >> 5;
    int mb     = blockIdx.x;        // 0..5
    int t0     = blockIdx.y * BN;
    int z      = blockIdx.z;

    if (tid == 0) {
        #pragma unroll
        for (int s = 0; s < NSTAGES; ++s) {
            mbar_init(mb_base + s * 8, 32);
            mbar_init(mb_base + 24 + s * 8, 8);
        }
    }
    __syncthreads();

    const int NT = 16;
    size_t aoff = ((size_t)l * 768 + mb * 128) * 512;

    if (wid == 8) {
        int ps = 0; uint32_t pp = 1;
        for (int t = 0; t < NT; ++t) {
            mbar_wait(mb_base + 24 + ps * 8, pp);
            int kt = t * 32;
            #pragma unroll 8
            for (int q = 0; q < 32; ++q) {
                int idx = q * 32 + lane;
                int pl  = idx >> 9;
                int rem = idx & 511;
                int row = rem >> 2;
                int kc  = rem & 3;
                const __nv_bfloat16* src = (pl ? d_WrsL : d_WrsH) + aoff
                                            + (size_t)row * 512 + kt + kc * 8;
                __nv_bfloat16* dst = pl ? &S[ps].AL[row][kc * 8] : &S[ps].AH[row][kc * 8];
                cp16(dst, src);
            }
            #pragma unroll 8
            for (int q = 0; q < 32; ++q) {
                int idx = q * 32 + lane;
                int pl  = idx >> 9;
                int rem = idx & 511;
                int row = rem >> 4;
                int c16 = rem & 15;
                const __nv_bfloat16* bp = pl ? d_gL : d_gH;
                const __nv_bfloat16* src = bp + (size_t)(kt + row) * BT + (size_t)z * TT
                                              + t0 + c16 * 8;
                __nv_bfloat16* dst = pl ? &S[ps].BL[row][c16 * 8] : &S[ps].BH[row][c16 * 8];
                cp16(dst, src);
            }
            cpasync_mbar_arrive(mb_base + ps * 8);
            if (++ps == NSTAGES) { ps = 0; pp ^= 1; }
        }
        return;
    }

    int warp_m = wid & 1;
    int warp_n = wid >> 1;
    int subA  = lane >> 3;
    int rowA  = (subA & 1) * 8 + (lane & 7);
    int kbA   = (subA >> 1) * 16;
    int rowB  = lane & 15;
    int colBq = (lane >> 4) * 16;

    float acc[4][4][4] = {};

    int cs = 0; uint32_t cp_ = 0;
    for (int t = 0; t < NT; ++t) {
        mbar_wait(mb_base + cs * 8, cp_);
        COMPUTE_TILE(S, cs, acc);
        __syncwarp();
        if (lane == 0) mbar_arrive(mb_base + 24 + cs * 8);
        if (++cs == NSTAGES) { cs = 0; cp_ ^= 1; }
    }

    int colbase = z * TT + t0 + warp_n * 32 + (lane & 3) * 2;
    #pragma unroll
    for (int mt = 0; mt < 4; ++mt) {
        int r0 = warp_m * 64 + mt * 16 + (lane >> 2);
        #pragma unroll
        for (int half = 0; half < 2; ++half) {
            int mg = mb * 128 + r0 + half * 8;
            float bias = d_brs[l * 768 + mg];
            #pragma unroll
            for (int nt = 0; nt < 4; ++nt) {
                int col = colbase + nt * 8;
                if (mg < 256) {
                    float* dst = &d_skip[(size_t)mg * BT + col];
                    float2 v = *(float2*)dst;
                    v.x += acc[mt][nt][half * 2 + 0] + bias;
                    v.y += acc[mt][nt][half * 2 + 1] + bias;
                    *(float2*)dst = v;
                } else {
                    int ch = mg - 256;
                    float* dst = &d_res[(size_t)ch * BT + col];
                    float2 v = *(float2*)dst;
                    v.x += acc[mt][nt][half * 2 + 0] + bias;
                    v.y += acc[mt][nt][half * 2 + 1] + bias;
                    *(float2*)dst = v;
                    uint2 w = split2(v.x, v.y);
                    size_t o = (size_t)ch * BT + col;
                    *(uint32_t*)&d_resH[o] = w.x;
                    *(uint32_t*)&d_resL[o] = w.y;
                    if (dnext) {
                        int tl = col - z * TT;
                        if (tl + dnext < TT)     splitHL(v.x, d_s1H, d_s1L, o + dnext);
                        if (tl + 1 + dnext < TT) splitHL(v.y, d_s1H, d_s1L, o + 1 + dnext);
                        __nv_bfloat16 zb = __float2bfloat16_rn(0.f);
                        if (tl < dnext)     { d_s1H[o] = zb;     d_s1L[o] = zb; }
                        if (tl + 1 < dnext) { d_s1H[o + 1] = zb; d_s1L[o + 1] = zb; }
                    }
                }
            }
        }
    }
}

// =====================================================================
// Post GEMMs (register-split path): M=256, N=8192, K=256
// =====================================================================
struct PostTiles {
    uint2 A[2][16][132];
    uint2 B[2][16][68];
};
#define POST_SMEM ((int)sizeof(PostTiles))

__device__ __forceinline__ void post_sts(PostTiles& S, int buf, int tid,
                                         const uint4* ra, float4 rb0, float4 rb1) {
    #pragma unroll
    for (int p = 0; p < 4; ++p) {
        int e  = tid + p * 256;
        int k2 = e >> 6;
        int m2 = (e & 63) << 1;
        *(uint4*)&S.A[buf][k2][m2] = ra[p];
    }
    int k2 = tid >> 4;
    int n4 = (tid & 15) << 2;
    const float* x0 = &rb0.x;
    const float* x1 = &rb1.x;
    #pragma unroll
    for (int j = 0; j < 4; ++j)
        S.B[buf][k2][n4 + j] = split2(x0[j], x1[j]);
}

#define POST_MMA3(acc, Ab, Bb, wm, wn, lane_)                                   \
    do {                                                                        \
        int c_ = (lane_) & 3, q_ = (lane_) >> 2;                                \
        _Pragma("unroll")                                                       \
        for (int ksb = 0; ksb < 2; ++ksb) {                                     \
            uint2 bw[2][2];                                                     \
            _Pragma("unroll")                                                   \
            for (int nt = 0; nt < 2; ++nt) {                                    \
                bw[nt][0] = (Bb)[ksb * 8 + c_][(wn) * 16 + nt * 8 + q_];        \
                bw[nt][1] = (Bb)[ksb * 8 + c_ + 4][(wn) * 16 + nt * 8 + q_];    \
            }                                                                   \
            _Pragma("unroll")                                                   \
            for (int mt = 0; mt < 4; ++mt) {                                    \
                int r_ = (wm) * 64 + mt * 16 + q_;                              \
                uint2 a0 = (Ab)[ksb * 8 + c_][r_];                              \
                uint2 a1 = (Ab)[ksb * 8 + c_][r_ + 8];                          \
                uint2 a2 = (Ab)[ksb * 8 + c_ + 4][r_];                          \
                uint2 a3 = (Ab)[ksb * 8 + c_ + 4][r_ + 8];                      \
                uint32_t ah_[4] = {a0.x, a1.x, a2.x, a3.x};                     \
                uint32_t al_[4] = {a0.y, a1.y, a2.y, a3.y};                     \
                uint32_t bh0_[2] = {bw[0][0].x, bw[0][1].x};                    \
                uint32_t bh1_[2] = {bw[1][0].x, bw[1][1].x};                    \
                uint32_t bl0_[2] = {bw[0][0].y, bw[0][1].y};                    \
                uint32_t bl1_[2] = {bw[1][0].y, bw[1][1].y};                    \
                mma16(acc[mt][0], ah_, bh0_);                                   \
                mma16(acc[mt][1], ah_, bh1_);                                   \
                mma16(acc[mt][0], ah_, bl0_);                                   \
                mma16(acc[mt][1], ah_, bl1_);                                   \
                mma16(acc[mt][0], al_, bh0_);                                   \
                mma16(acc[mt][1], al_, bh1_);                                   \
            }                                                                   \
        }                                                                       \
    } while (0)

__global__ __launch_bounds__(256, 2)
void post_k(int mode, const float* __restrict__ bias, float* __restrict__ outp) {
    extern __shared__ uint8_t smraw[];
    PostTiles& S = *reinterpret_cast<PostTiles*>(smraw);

    int tid    = threadIdx.x;
    int lane   = tid & 31;
    int wid    = tid >> 5;
    int warp_m = wid & 1;
    int warp_n = wid >> 1;
    int mb     = blockIdx.x;
    int j0     = blockIdx.y * 64;

    const uint2* A    = (mode == 1) ? d_Wp12 : (mode == 2) ? d_Wp22 : d_Wp32;
    const float* Bsrc = (mode == 2) ? d_o1 : d_skip;

    float acc[4][2][4] = {};
    uint4  ra[4];
    float4 rb0, rb1;

    auto FETCH = [&](int tile) {
        #pragma unroll
        for (int p = 0; p < 4; ++p) {
            int e  = tid + p * 256;
            int k2 = e >> 6;
            int m2 = (e & 63) << 1;
            ra[p] = *(const uint4*)&A[(size_t)(tile * 16 + k2) * 256 + mb * 128 + m2];
        }
        int k2 = tid >> 4;
        int n4 = (tid & 15) << 2;
        int k0 = tile * 32 + 2 * k2;
        rb0 = *(const float4*)&Bsrc[(size_t)k0 * BT + j0 + n4];
        rb1 = *(const float4*)&Bsrc[(size_t)(k0 + 1) * BT + j0 + n4];
        if (mode == 1) {
            rb0.x = fmaxf(rb0.x, 0.f); rb0.y = fmaxf(rb0.y, 0.f);
            rb0.z = fmaxf(rb0.z, 0.f); rb0.w = fmaxf(rb0.w, 0.f);
            rb1.x = fmaxf(rb1.x, 0.f); rb1.y = fmaxf(rb1.y, 0.f);
            rb1.z = fmaxf(rb1.z, 0.f); rb1.w = fmaxf(rb1.w, 0.f);
        }
    };

    FETCH(0);
    post_sts(S, 0, tid, ra, rb0, rb1);
    __syncthreads();

    const int NT = 8;
    for (int t = 0; t < NT; ++t) {
        if (t + 1 < NT) FETCH(t + 1);
        POST_MMA3(acc, S.A[t & 1], S.B[t & 1], warp_m, warp_n, lane);
        if (t + 1 < NT) post_sts(S, (t + 1) & 1, tid, ra, rb0, rb1);
        __syncthreads();
    }

    int colbase = j0 + warp_n * 16 + (lane & 3) * 2;
    #pragma unroll
    for (int mt = 0; mt < 4; ++mt) {
        int r0 = warp_m * 64 + mt * 16 + (lane >> 2);
        #pragma unroll
        for (int half = 0; half < 2; ++half) {
            int mg = mb * 128 + r0 + half * 8;
            float bv = bias[mg];
            #pragma unroll
            for (int nt = 0; nt < 2; ++nt) {
                float v0 = acc[mt][nt][half * 2 + 0] + bv;
                float v1 = acc[mt][nt][half * 2 + 1] + bv;
                if (mode == 1) { v0 = fmaxf(v0, 0.f); v1 = fmaxf(v1, 0.f); }
                int col = colbase + nt * 8;
                if (mode == 3) {
                    outp[(size_t)(col    ) * NQ + mg] = v0;
                    outp[(size_t)(col + 1) * NQ + mg] = v1;
                } else {
                    float* dst = (mode == 1) ? &d_o1[(size_t)mg * BT + col]
                                             : &d_skip[(size_t)mg * BT + col];
                    *(float2*)dst = make_float2(v0, v1);
                }
            }
        }
    }
}

// =====================================================================
// Launch
// =====================================================================
extern "C" void kernel_launch(void* const* d_in, const int* in_sizes, int n_in,
                              void* d_out, int out_size) {
    const int*   x          = (const int*)  d_in[0];
    const float* h          = (const float*)d_in[1];
    const float* causal_w   = (const float*)d_in[2];
    const float* causal_b   = (const float*)d_in[3];
    const float* dil_sig_w  = (const float*)d_in[4];
    const float* dil_sig_b  = (const float*)d_in[5];
    const float* dil_tanh_w = (const float*)d_in[6];
    const float* dil_tanh_b = (const float*)d_in[7];
    const float* aux_sig_w  = (const float*)d_in[8];
    const float* aux_sig_b  = (const float*)d_in[9];
    const float* aux_tanh_w = (const float*)d_in[10];
    const float* aux_tanh_b = (const float*)d_in[11];
    const float* skip_w     = (const float*)d_in[12];
    const float* skip_b     = (const float*)d_in[13];
    const float* res_w      = (const float*)d_in[14];
    const float* res_b      = (const float*)d_in[15];
    const float* post1_w    = (const float*)d_in[16];
    const float* post1_b    = (const float*)d_in[17];
    const float* post2_w    = (const float*)d_in[18];
    const float* post2_b    = (const float*)d_in[19];
    const float* lin_w      = (const float*)d_in[20];
    const float* lin_b      = (const float*)d_in[21];

    cudaFuncSetAttribute(gate_k,    cudaFuncAttributeMaxDynamicSharedMemorySize, GEMM_SMEM);
    cudaFuncSetAttribute(skipres_k, cudaFuncAttributeMaxDynamicSharedMemorySize, GEMM_SMEM);
    cudaFuncSetAttribute(post_k,    cudaFuncAttributeMaxDynamicSharedMemorySize, POST_SMEM);

    {
        size_t n = PACK_TOTAL;
        pack_all_k<<<(unsigned)((n + 255) / 256), 256>>>(
            dil_sig_w, dil_tanh_w, aux_sig_w, aux_tanh_w, skip_w, res_w,
            dil_sig_b, dil_tanh_b, aux_sig_b, aux_tanh_b, skip_b, res_b,
            post1_w, post2_w, lin_w, h);
    }
    zero_skip_k<<<(NS * BT + 255) / 256, 256>>>();
    embed_k<<<dim3(BT / 256, NR), 256>>>(x, causal_w, causal_b);

    for (int l = 0; l < NLAYERS; ++l) {
        int d = 1 << (l % 10);
        int useS1 = (d < 8);
        int dn = (l + 1 < NLAYERS) ? (1 << ((l + 1) % 10)) : 0;
        if (dn >= 8) dn = 0;
        gate_k   <<<dim3(8, TT / BN, BATCH), NTHREADS, GEMM_SMEM>>>(l, d, useS1);
        skipres_k<<<dim3(6, TT / BN, BATCH), NTHREADS, GEMM_SMEM>>>(l, dn);
    }

    post_k<<<dim3(2, BT / 64), 256, POST_SMEM>>>(1, post1_b, nullptr);
    post_k<<<dim3(2, BT / 64), 256, POST_SMEM>>>(2, post2_b, nullptr);
    post_k<<<dim3(2, BT / 64), 256, POST_SMEM>>>(3, lin_b, (float*)d_out);
}

// round 15
// speedup vs baseline: 1.0197x; 1.0197x over previous
#include <cuda_runtime.h>
#include <cuda_bf16.h>
#include <math.h>
#include <stdint.h>

// ---------------- problem constants ----------------
#define BATCH   2
#define TT      4096
#define BT      8192
#define NQ      256
#define NAUX    28
#define NR      512
#define NS      256
#define NLAYERS 30

// ---------------- main GEMM tiling ----------------
#define BM 128
#define BN 128
#define NTHREADS 256
#define NSTAGES 3

// smem strides (elements)
#define SA 40        // A row: 32 k + 8 pad
#define SB 136       // B row: 128 n + 8 pad

// ---------------- device scratch ----------------
__device__ float d_res [NR * BT];
__device__ float d_o1  [NS * BT];
__device__ float d_skip[NS * BT];

__device__ __nv_bfloat16 d_resH[NR * BT], d_resL[NR * BT];
__device__ __nv_bfloat16 d_s1H [NR * BT], d_s1L [NR * BT];
__device__ __nv_bfloat16 d_gH  [NR * BT], d_gL  [NR * BT];
__device__ __nv_bfloat16 d_hH  [32 * BT], d_hL  [32 * BT];

__device__ __nv_bfloat16 d_WgH [NLAYERS * 2 * 1024 * 512], d_WgL [NLAYERS * 2 * 1024 * 512];
__device__ __nv_bfloat16 d_WaH [NLAYERS * 1024 * 32],      d_WaL [NLAYERS * 1024 * 32];
__device__ __nv_bfloat16 d_WrsH[NLAYERS * 768 * 512],      d_WrsL[NLAYERS * 768 * 512];

__device__ float d_bg [NLAYERS * 1024];
__device__ float d_brs[NLAYERS * 768];

__device__ uint2 d_Wp12[128 * 256];
__device__ uint2 d_Wp22[128 * 256];
__device__ uint2 d_Wp32[128 * 256];

// ---------------- helpers ----------------
__device__ __forceinline__ uint32_t pk2(__nv_bfloat16 a, __nv_bfloat16 b) {
    return (uint32_t)__bfloat16_as_ushort(a) | ((uint32_t)__bfloat16_as_ushort(b) << 16);
}

__device__ __forceinline__ uint2 split2(float x, float y) {
    __nv_bfloat16 xh = __float2bfloat16_rn(x);
    __nv_bfloat16 yh = __float2bfloat16_rn(y);
    __nv_bfloat16 xl = __float2bfloat16_rn(x - __bfloat162float(xh));
    __nv_bfloat16 yl = __float2bfloat16_rn(y - __bfloat162float(yh));
    uint2 w; w.x = pk2(xh, yh); w.y = pk2(xl, yl); return w;
}

__device__ __forceinline__ void splitHL(float v, __nv_bfloat16* H, __nv_bfloat16* L, size_t o) {
    __nv_bfloat16 hh = __float2bfloat16_rn(v);
    H[o] = hh; L[o] = __float2bfloat16_rn(v - __bfloat162float(hh));
}

__device__ __forceinline__ void mma16(float* c, const uint32_t* a, const uint32_t* b) {
    asm volatile(
        "mma.sync.aligned.m16n8k16.row.col.f32.bf16.bf16.f32 "
        "{%0,%1,%2,%3}, {%4,%5,%6,%7}, {%8,%9}, {%0,%1,%2,%3};\n"
        : "+f"(c[0]), "+f"(c[1]), "+f"(c[2]), "+f"(c[3])
        : "r"(a[0]), "r"(a[1]), "r"(a[2]), "r"(a[3]), "r"(b[0]), "r"(b[1]));
}

__device__ __forceinline__ void ldm_x4(uint32_t* r, uint32_t saddr) {
    asm volatile("ldmatrix.sync.aligned.m8n8.x4.shared.b16 {%0,%1,%2,%3}, [%4];"
        : "=r"(r[0]), "=r"(r[1]), "=r"(r[2]), "=r"(r[3]) : "r"(saddr));
}
__device__ __forceinline__ void ldm_x4t(uint32_t* r, uint32_t saddr) {
    asm volatile("ldmatrix.sync.aligned.m8n8.x4.trans.shared.b16 {%0,%1,%2,%3}, [%4];"
        : "=r"(r[0]), "=r"(r[1]), "=r"(r[2]), "=r"(r[3]) : "r"(saddr));
}

__device__ __forceinline__ void cp16(void* dst, const void* src) {
    uint32_t s = (uint32_t)__cvta_generic_to_shared(dst);
    asm volatile("cp.async.cg.shared.global [%0], [%1], 16;\n" :: "r"(s), "l"(src));
}
__device__ __forceinline__ void cp16z(void* dst, const void* src, int valid) {
    uint32_t s = (uint32_t)__cvta_generic_to_shared(dst);
    asm volatile("cp.async.cg.shared.global [%0], [%1], 16, %2;\n"
                 :: "r"(s), "l"(src), "r"(valid ? 16 : 0));
}
__device__ __forceinline__ void cp_commit() {
    asm volatile("cp.async.commit_group;\n" ::: "memory");
}
__device__ __forceinline__ void cp_wait1() {
    asm volatile("cp.async.wait_group 1;\n" ::: "memory");
}
__device__ __forceinline__ void cp_wait0() {
    asm volatile("cp.async.wait_group 0;\n" ::: "memory");
}

__device__ __forceinline__ int gate_channel_of_row(int mlocal) {
    return ((mlocal >> 4) << 3) | (mlocal & 7);
}
__device__ __forceinline__ int gate_c_of_m(int m) {
    int mlocal = m & 127;
    int cc = gate_channel_of_row(mlocal & ~8);
    return (m >> 7) * 64 + cc;
}
__device__ __forceinline__ int gate_half_of_m(int m) { return (m >> 3) & 1; }

struct Stage {
    __nv_bfloat16 AH[128][SA];
    __nv_bfloat16 AL[128][SA];
    __nv_bfloat16 BH[32][SB];
    __nv_bfloat16 BL[32][SB];
};
static_assert(sizeof(Stage) == 37888, "stage size");
#define GEMM_SMEM (NSTAGES * (int)sizeof(Stage))     // 113664

// =====================================================================
// ONE merged packing kernel
// =====================================================================
__global__ void pack_all_k(const float* __restrict__ dsw, const float* __restrict__ dtw,
                           const float* __restrict__ asw, const float* __restrict__ atw,
                           const float* __restrict__ skw, const float* __restrict__ rew,
                           const float* __restrict__ dsb, const float* __restrict__ dtb,
                           const float* __restrict__ asb, const float* __restrict__ atb,
                           const float* __restrict__ skb, const float* __restrict__ reb,
                           const float* __restrict__ p1w, const float* __restrict__ p2w,
                           const float* __restrict__ p3w, const float* __restrict__ h) {
    size_t gi = (size_t)blockIdx.x * blockDim.x + threadIdx.x;
    const size_t N1 = (size_t)NLAYERS * 2 * 1024 * 512;
    const size_t N2 = (size_t)NLAYERS * 1024 * 32;
    const size_t N3 = (size_t)NLAYERS * 768 * 512;
    const size_t N4 = (size_t)NLAYERS * (1024 + 768);
    const size_t N5 = 3 * 128 * 256;
    const size_t N6 = (size_t)32 * BT;

    if (gi < N1) {
        int idx = (int)gi;
        int k = idx & 511, rm = idx >> 9;
        int m = rm & 1023, lt = rm >> 10;
        int tap = lt & 1, l = lt >> 1, c = gate_c_of_m(m);
        const float* src = gate_half_of_m(m) ? dtw : dsw;
        splitHL(src[((size_t)(l * NR + c) * NR + k) * 2 + tap], d_WgH, d_WgL, idx);
        return;
    }
    gi -= N1;
    if (gi < N2) {
        int idx = (int)gi;
        int k = idx & 31, rm = idx >> 5;
        int m = rm & 1023, l = rm >> 10, c = gate_c_of_m(m);
        const float* src = gate_half_of_m(m) ? atw : asw;
        splitHL((k < NAUX) ? src[(size_t)(l * NR + c) * NAUX + k] : 0.f, d_WaH, d_WaL, idx);
        return;
    }
    gi -= N2;
    if (gi < N3) {
        int idx = (int)gi;
        int k = idx & 511, rm = idx >> 9;
        int m = rm % 768, l = rm / 768;
        float v = (m < 256) ? skw[(size_t)(l * NS + m) * NR + k]
                            : rew[(size_t)(l * NR + (m - 256)) * NR + k];
        splitHL(v, d_WrsH, d_WrsL, idx);
        return;
    }
    gi -= N3;
    if (gi < N4) {
        int idx = (int)gi;
        if (idx < NLAYERS * 1024) {
            int l = idx >> 10, m = idx & 1023, c = gate_c_of_m(m);
            d_bg[idx] = gate_half_of_m(m) ? (dtb[l * NR + c] + atb[l * NR + c])
                                          : (dsb[l * NR + c] + asb[l * NR + c]);
        } else {
            int j = idx - NLAYERS * 1024;
            int l = j / 768, m = j % 768;
            d_brs[j] = (m < 256) ? skb[l * NS + m] : reb[l * NR + (m - 256)];
        }
        return;
    }
    gi -= N4;
    if (gi < N5) {
        int idx = (int)gi;
        int w = idx / 32768, r = idx % 32768;
        int k2 = r >> 8, m = r & 255;
        const float* p = (w == 0) ? p1w : (w == 1) ? p2w : p3w;
        uint2 v = split2(p[m * 256 + 2 * k2], p[m * 256 + 2 * k2 + 1]);
        if (w == 0)      d_Wp12[r] = v;
        else if (w == 1) d_Wp22[r] = v;
        else             d_Wp32[r] = v;
        return;
    }
    gi -= N5;
    if (gi < N6) {
        int idx = (int)gi;
        int a = idx / BT, j = idx % BT;
        float v = 0.f;
        if (a < NAUX) {
            int b = j >> 12, t = j & (TT - 1);
            v = h[((size_t)b * NAUX + a) * TT + t];
        }
        splitHL(v, d_hH, d_hL, idx);
    }
}
#define PACK_TOTAL ((size_t)NLAYERS*2*1024*512 + (size_t)NLAYERS*1024*32 + \
                    (size_t)NLAYERS*768*512 + (size_t)NLAYERS*(1024+768) + \
                    3*128*256 + (size_t)32*BT)

__global__ void zero_skip_k() {
    int idx = blockIdx.x * blockDim.x + threadIdx.x;
    if (idx < NS * BT) d_skip[idx] = 0.f;
}

// =====================================================================
// Embedding -> res fp32 + planes + s1 (layer0 d=1)
// =====================================================================
__global__ void embed_k(const int* __restrict__ x, const float* __restrict__ cw,
                        const float* __restrict__ cb) {
    int j = blockIdx.x * blockDim.x + threadIdx.x;
    int c = blockIdx.y;
    if (j >= BT) return;
    int b = j >> 12;
    int t = j & (TT - 1);
    int q1 = x[b * TT + t] & 255;
    float v = cw[(c * NQ + q1) * 2 + 1] + cb[c];
    if (t > 0) {
        int q0 = x[b * TT + t - 1] & 255;
        v += cw[(c * NQ + q0) * 2 + 0];
    }
    size_t o = (size_t)c * BT + j;
    d_res[o] = v;
    splitHL(v, d_resH, d_resL, o);
    if (t + 1 < TT) splitHL(v, d_s1H, d_s1L, o + 1);
    if (t == 0) {
        __nv_bfloat16 z = __float2bfloat16_rn(0.f);
        d_s1H[o] = z; d_s1L[o] = z;
    }
}

// =====================================================================
// Gate GEMM (R11 exact): M=1024, N=8192, K = 512+512+32
// =====================================================================
__global__ __launch_bounds__(NTHREADS, 2)
void gate_k(int l, int d, int useS1) {
    extern __shared__ uint8_t smraw[];
    Stage* S = reinterpret_cast<Stage*>(smraw);

    int tid    = threadIdx.x;
    int lane   = tid & 31;
    int wid    = tid >> 5;
    int warp_m = wid & 1;
    int warp_n = wid >> 1;
    int mb     = blockIdx.x;
    int t0     = blockIdx.y * BN;
    int z      = blockIdx.z;

    float acc[4][4][4] = {};

    int subA  = lane >> 3;
    int rowA  = (subA & 1) * 8 + (lane & 7);
    int kbA   = (subA >> 1) * 16;
    int rowB  = lane & 15;
    int colBq = (lane >> 4) * 16;

    auto fillA = [&](int stage, int tile) {
        const __nv_bfloat16 *PH, *PL;
        int rowstride;
        if (tile < 32) {
            int tap = tile >> 4;
            int kt  = (tile & 15) * 32;
            size_t off = ((size_t)((l * 2 + tap) * 1024) + mb * 128) * 512 + kt;
            PH = d_WgH + off; PL = d_WgL + off; rowstride = 512;
        } else {
            size_t off = ((size_t)l * 1024 + mb * 128) * 32;
            PH = d_WaH + off; PL = d_WaL + off; rowstride = 32;
        }
        #pragma unroll
        for (int p = 0; p < 4; ++p) {
            int idx = tid + p * 256;
            int pl  = idx >> 9;
            int rem = idx & 511;
            int row = rem >> 2;
            int kc  = rem & 3;
            const __nv_bfloat16* src = (pl ? PL : PH) + (size_t)row * rowstride + kc * 8;
            __nv_bfloat16* dst = pl ? &S[stage].AL[row][kc * 8] : &S[stage].AH[row][kc * 8];
            cp16(dst, src);
        }
    };

    auto fillB = [&](int stage, int tile) {
        const __nv_bfloat16 *baseH, *baseL;
        int kt, doff;
        if (tile < 16) {
            baseH = useS1 ? d_s1H : d_resH;
            baseL = useS1 ? d_s1L : d_resL;
            kt = tile * 32; doff = useS1 ? 0 : d;
        } else if (tile < 32) {
            baseH = d_resH; baseL = d_resL; kt = (tile - 16) * 32; doff = 0;
        } else {
            baseH = d_hH; baseL = d_hL; kt = 0; doff = 0;
        }
        #pragma unroll
        for (int p = 0; p < 4; ++p) {
            int idx = tid + p * 256;
            int pl  = idx >> 9;
            int rem = idx & 511;
            int row = rem >> 4;
            int c16 = rem & 15;
            int col = t0 + c16 * 8 - doff;
            const __nv_bfloat16* bp = pl ? baseL : baseH;
            const __nv_bfloat16* src = bp + (size_t)(kt + row) * BT + (size_t)z * TT
                                          + (col >= 0 ? col : 0);
            __nv_bfloat16* dst = pl ? &S[stage].BL[row][c16 * 8] : &S[stage].BH[row][c16 * 8];
            cp16z(dst, src, col >= 0);
        }
    };

    auto compute = [&](int stage) {
        uint32_t aH = (uint32_t)__cvta_generic_to_shared(&S[stage].AH[0][0]);
        uint32_t aL = (uint32_t)__cvta_generic_to_shared(&S[stage].AL[0][0]);
        uint32_t bH = (uint32_t)__cvta_generic_to_shared(&S[stage].BH[0][0]);
        uint32_t bL = (uint32_t)__cvta_generic_to_shared(&S[stage].BL[0][0]);
        #pragma unroll
        for (int k16 = 0; k16 < 2; ++k16) {
            uint32_t bfH[2][4], bfL[2][4];
            #pragma unroll
            for (int hh = 0; hh < 2; ++hh) {
                uint32_t boff = (uint32_t)((k16 * 16 + rowB) * (SB * 2)
                                           + warp_n * 64 + hh * 32 + colBq);
                ldm_x4t(bfH[hh], bH + boff);
                ldm_x4t(bfL[hh], bL + boff);
            }
            #pragma unroll
            for (int mt = 0; mt < 4; ++mt) {
                uint32_t afH[4], afL[4];
                uint32_t off = (uint32_t)((warp_m * 64 + mt * 16 + rowA) * (SA * 2)
                                          + k16 * 32 + kbA);
                ldm_x4(afH, aH + off);
                ldm_x4(afL, aL + off);
                #pragma unroll
                for (int nt = 0; nt < 4; ++nt)
                    mma16(acc[mt][nt], afH, bfH[nt >> 1] + (nt & 1) * 2);
                #pragma unroll
                for (int nt = 0; nt < 4; ++nt)
                    mma16(acc[mt][nt], afH, bfL[nt >> 1] + (nt & 1) * 2);
                #pragma unroll
                for (int nt = 0; nt < 4; ++nt)
                    mma16(acc[mt][nt], afL, bfH[nt >> 1] + (nt & 1) * 2);
            }
        }
    };

    const int NT = 33;
    fillA(0, 0); fillB(0, 0); cp_commit();
    fillA(1, 1); fillB(1, 1); cp_commit();
    for (int t = 0; t < NT; ++t) {
        if (t + 1 < NT) cp_wait1(); else cp_wait0();
        __syncthreads();
        if (t + 2 < NT) {
            int s2 = (t + 2) % 3;
            fillA(s2, t + 2); fillB(s2, t + 2); cp_commit();
        }
        compute(t % 3);
    }

    // gated activation epilogue -> g planes
    const float* bgp = d_bg + l * 1024 + mb * 128;
    int colbase = z * TT + t0 + warp_n * 32 + (lane & 3) * 2;
    #pragma unroll
    for (int mt = 0; mt < 4; ++mt) {
        int r  = warp_m * 64 + mt * 16 + (lane >> 2);
        int cc = gate_channel_of_row(r);
        int cg = mb * 64 + cc;
        float bs = bgp[r];
        float bt = bgp[r + 8];
        #pragma unroll
        for (int nt = 0; nt < 4; ++nt) {
            float s0  = acc[mt][nt][0] + bs;
            float s1  = acc[mt][nt][1] + bs;
            float tv0 = acc[mt][nt][2] + bt;
            float tv1 = acc[mt][nt][3] + bt;
            float g0 = __fdividef(1.f, 1.f + __expf(-s0)) *
                       (1.f - __fdividef(2.f, __expf(2.f * tv0) + 1.f));
            float g1 = __fdividef(1.f, 1.f + __expf(-s1)) *
                       (1.f - __fdividef(2.f, __expf(2.f * tv1) + 1.f));
            uint2 w = split2(g0, g1);
            size_t o = (size_t)cg * BT + colbase + nt * 8;
            *(uint32_t*)&d_gH[o] = w.x;
            *(uint32_t*)&d_gL[o] = w.y;
        }
    }
}

// =====================================================================
// Skip/Res GEMM: BM=128 x BN=64 (grid 768); fillB FIXED (full coverage)
// =====================================================================
__global__ __launch_bounds__(NTHREADS, 2)
void skipres_k(int l, int dnext) {
    extern __shared__ uint8_t smraw[];
    Stage* S = reinterpret_cast<Stage*>(smraw);

    int tid    = threadIdx.x;
    int lane   = tid & 31;
    int wid    = tid >> 5;
    int warp_m = wid & 1;
    int warp_n = wid >> 1;
    int mb     = blockIdx.x;       // 0..5
    int t0     = blockIdx.y * 64;  // BN=64
    int z      = blockIdx.z;

    float acc[4][2][4] = {};

    int subA  = lane >> 3;
    int rowA  = (subA & 1) * 8 + (lane & 7);
    int kbA   = (subA >> 1) * 16;
    int rowB  = lane & 15;
    int colBq = (lane >> 4) * 16;

    size_t aoff = ((size_t)l * 768 + mb * 128) * 512;

    auto fillA = [&](int stage, int tile) {
        int kt = tile * 32;
        #pragma unroll
        for (int p = 0; p < 4; ++p) {
            int idx = tid + p * 256;
            int pl  = idx >> 9;
            int rem = idx & 511;
            int row = rem >> 2;
            int kc  = rem & 3;
            const __nv_bfloat16* src = (pl ? d_WrsL : d_WrsH) + aoff
                                        + (size_t)row * 512 + kt + kc * 8;
            __nv_bfloat16* dst = pl ? &S[stage].AL[row][kc * 8] : &S[stage].AH[row][kc * 8];
            cp16(dst, src);
        }
    };
    auto fillB = [&](int stage, int tile) {
        int kt = tile * 32;
        // 32 rows x 64 cols x 2 planes = 512 chunks of 16B; 2 per thread.
        #pragma unroll
        for (int p = 0; p < 2; ++p) {
            int idx = tid + p * 256;
            int pl  = idx >> 8;          // 0: H plane, 1: L plane
            int rem = idx & 255;
            int row = rem >> 3;          // 0..31
            int c8  = (rem & 7) * 8;     // 0..56 (covers all 64 cols)
            const __nv_bfloat16* bp = pl ? d_gL : d_gH;
            const __nv_bfloat16* src = bp + (size_t)(kt + row) * BT + (size_t)z * TT + t0 + c8;
            __nv_bfloat16* dst = pl ? &S[stage].BL[row][c8] : &S[stage].BH[row][c8];
            cp16(dst, src);
        }
    };
    auto compute = [&](int stage) {
        uint32_t aH = (uint32_t)__cvta_generic_to_shared(&S[stage].AH[0][0]);
        uint32_t aL = (uint32_t)__cvta_generic_to_shared(&S[stage].AL[0][0]);
        uint32_t bH = (uint32_t)__cvta_generic_to_shared(&S[stage].BH[0][0]);
        uint32_t bL = (uint32_t)__cvta_generic_to_shared(&S[stage].BL[0][0]);
        #pragma unroll
        for (int k16 = 0; k16 < 2; ++k16) {
            uint32_t bfH[4], bfL[4];
            uint32_t boff = (uint32_t)((k16 * 16 + rowB) * (SB * 2)
                                       + warp_n * 32 + colBq);
            ldm_x4t(bfH, bH + boff);
            ldm_x4t(bfL, bL + boff);
            #pragma unroll
            for (int mt = 0; mt < 4; ++mt) {
                uint32_t afH[4], afL[4];
                uint32_t off = (uint32_t)((warp_m * 64 + mt * 16 + rowA) * (SA * 2)
                                          + k16 * 32 + kbA);
                ldm_x4(afH, aH + off);
                ldm_x4(afL, aL + off);
                #pragma unroll
                for (int nt = 0; nt < 2; ++nt)
                    mma16(acc[mt][nt], afH, bfH + nt * 2);
                #pragma unroll
                for (int nt = 0; nt < 2; ++nt)
                    mma16(acc[mt][nt], afH, bfL + nt * 2);
                #pragma unroll
                for (int nt = 0; nt < 2; ++nt)
                    mma16(acc[mt][nt], afL, bfH + nt * 2);
            }
        }
    };

    const int NT = 16;
    fillA(0, 0); fillB(0, 0); cp_commit();
    fillA(1, 1); fillB(1, 1); cp_commit();
    for (int t = 0; t < NT; ++t) {
        if (t + 1 < NT) cp_wait1(); else cp_wait0();
        __syncthreads();
        if (t + 2 < NT) {
            int s2 = (t + 2) % 3;
            fillA(s2, t + 2); fillB(s2, t + 2); cp_commit();
        }
        compute(t % 3);
    }

    int colbase = z * TT + t0 + warp_n * 16 + (lane & 3) * 2;
    #pragma unroll
    for (int mt = 0; mt < 4; ++mt) {
        int r0 = warp_m * 64 + mt * 16 + (lane >> 2);
        #pragma unroll
        for (int half = 0; half < 2; ++half) {
            int mg = mb * 128 + r0 + half * 8;
            float bias = d_brs[l * 768 + mg];
            #pragma unroll
            for (int nt = 0; nt < 2; ++nt) {
                int col = colbase + nt * 8;
                if (mg < 256) {
                    float* dst = &d_skip[(size_t)mg * BT + col];
                    float2 v = *(float2*)dst;
                    v.x += acc[mt][nt][half * 2 + 0] + bias;
                    v.y += acc[mt][nt][half * 2 + 1] + bias;
                    *(float2*)dst = v;
                } else {
                    int ch = mg - 256;
                    float* dst = &d_res[(size_t)ch * BT + col];
                    float2 v = *(float2*)dst;
                    v.x += acc[mt][nt][half * 2 + 0] + bias;
                    v.y += acc[mt][nt][half * 2 + 1] + bias;
                    *(float2*)dst = v;
                    uint2 w = split2(v.x, v.y);
                    size_t o = (size_t)ch * BT + col;
                    *(uint32_t*)&d_resH[o] = w.x;
                    *(uint32_t*)&d_resL[o] = w.y;
                    if (dnext) {
                        int tl = col - z * TT;
                        if (tl + dnext < TT)     splitHL(v.x, d_s1H, d_s1L, o + dnext);
                        if (tl + 1 + dnext < TT) splitHL(v.y, d_s1H, d_s1L, o + 1 + dnext);
                        __nv_bfloat16 zb = __float2bfloat16_rn(0.f);
                        if (tl < dnext)     { d_s1H[o] = zb;     d_s1L[o] = zb; }
                        if (tl + 1 < dnext) { d_s1H[o + 1] = zb; d_s1L[o + 1] = zb; }
                    }
                }
            }
        }
    }
}

// =====================================================================
// Post GEMMs (register-split path): M=256, N=8192, K=256
// =====================================================================
struct PostTiles {
    uint2 A[2][16][132];
    uint2 B[2][16][68];
};
#define POST_SMEM ((int)sizeof(PostTiles))

__device__ __forceinline__ void post_sts(PostTiles& S, int buf, int tid,
                                         const uint4* ra, float4 rb0, float4 rb1) {
    #pragma unroll
    for (int p = 0; p < 4; ++p) {
        int e  = tid + p * 256;
        int k2 = e >> 6;
        int m2 = (e & 63) << 1;
        *(uint4*)&S.A[buf][k2][m2] = ra[p];
    }
    int k2 = tid >> 4;
    int n4 = (tid & 15) << 2;
    const float* x0 = &rb0.x;
    const float* x1 = &rb1.x;
    #pragma unroll
    for (int j = 0; j < 4; ++j)
        S.B[buf][k2][n4 + j] = split2(x0[j], x1[j]);
}

#define POST_MMA3(acc, Ab, Bb, wm, wn, lane_)                                   \
    do {                                                                        \
        int c_ = (lane_) & 3, q_ = (lane_) >> 2;                                \
        _Pragma("unroll")                                                       \
        for (int ksb = 0; ksb < 2; ++ksb) {                                     \
            uint2 bw[2][2];                                                     \
            _Pragma("unroll")                                                   \
            for (int nt = 0; nt < 2; ++nt) {                                    \
                bw[nt][0] = (Bb)[ksb * 8 + c_][(wn) * 16 + nt * 8 + q_];        \
                bw[nt][1] = (Bb)[ksb * 8 + c_ + 4][(wn) * 16 + nt * 8 + q_];    \
            }                                                                   \
            _Pragma("unroll")                                                   \
            for (int mt = 0; mt < 4; ++mt) {                                    \
                int r_ = (wm) * 64 + mt * 16 + q_;                              \
                uint2 a0 = (Ab)[ksb * 8 + c_][r_];                              \
                uint2 a1 = (Ab)[ksb * 8 + c_][r_ + 8];                          \
                uint2 a2 = (Ab)[ksb * 8 + c_ + 4][r_];                          \
                uint2 a3 = (Ab)[ksb * 8 + c_ + 4][r_ + 8];                      \
                uint32_t ah_[4] = {a0.x, a1.x, a2.x, a3.x};                     \
                uint32_t al_[4] = {a0.y, a1.y, a2.y, a3.y};                     \
                uint32_t bh0_[2] = {bw[0][0].x, bw[0][1].x};                    \
                uint32_t bh1_[2] = {bw[1][0].x, bw[1][1].x};                    \
                uint32_t bl0_[2] = {bw[0][0].y, bw[0][1].y};                    \
                uint32_t bl1_[2] = {bw[1][0].y, bw[1][1].y};                    \
                mma16(acc[mt][0], ah_, bh0_);                                   \
                mma16(acc[mt][1], ah_, bh1_);                                   \
                mma16(acc[mt][0], ah_, bl0_);                                   \
                mma16(acc[mt][1], ah_, bl1_);                                   \
                mma16(acc[mt][0], al_, bh0_);                                   \
                mma16(acc[mt][1], al_, bh1_);                                   \
            }                                                                   \
        }                                                                       \
    } while (0)

__global__ __launch_bounds__(256, 2)
void post_k(int mode, const float* __restrict__ bias, float* __restrict__ outp) {
    extern __shared__ uint8_t smraw[];
    PostTiles& S = *reinterpret_cast<PostTiles*>(smraw);

    int tid    = threadIdx.x;
    int lane   = tid & 31;
    int wid    = tid >> 5;
    int warp_m = wid & 1;
    int warp_n = wid >> 1;
    int mb     = blockIdx.x;
    int j0     = blockIdx.y * 64;

    const uint2* A    = (mode == 1) ? d_Wp12 : (mode == 2) ? d_Wp22 : d_Wp32;
    const float* Bsrc = (mode == 2) ? d_o1 : d_skip;

    float acc[4][2][4] = {};
    uint4  ra[4];
    float4 rb0, rb1;

    auto FETCH = [&](int tile) {
        #pragma unroll
        for (int p = 0; p < 4; ++p) {
            int e  = tid + p * 256;
            int k2 = e >> 6;
            int m2 = (e & 63) << 1;
            ra[p] = *(const uint4*)&A[(size_t)(tile * 16 + k2) * 256 + mb * 128 + m2];
        }
        int k2 = tid >> 4;
        int n4 = (tid & 15) << 2;
        int k0 = tile * 32 + 2 * k2;
        rb0 = *(const float4*)&Bsrc[(size_t)k0 * BT + j0 + n4];
        rb1 = *(const float4*)&Bsrc[(size_t)(k0 + 1) * BT + j0 + n4];
        if (mode == 1) {
            rb0.x = fmaxf(rb0.x, 0.f); rb0.y = fmaxf(rb0.y, 0.f);
            rb0.z = fmaxf(rb0.z, 0.f); rb0.w = fmaxf(rb0.w, 0.f);
            rb1.x = fmaxf(rb1.x, 0.f); rb1.y = fmaxf(rb1.y, 0.f);
            rb1.z = fmaxf(rb1.z, 0.f); rb1.w = fmaxf(rb1.w, 0.f);
        }
    };

    FETCH(0);
    post_sts(S, 0, tid, ra, rb0, rb1);
    __syncthreads();

    const int NT = 8;
    for (int t = 0; t < NT; ++t) {
        if (t + 1 < NT) FETCH(t + 1);
        POST_MMA3(acc, S.A[t & 1], S.B[t & 1], warp_m, warp_n, lane);
        if (t + 1 < NT) post_sts(S, (t + 1) & 1, tid, ra, rb0, rb1);
        __syncthreads();
    }

    int colbase = j0 + warp_n * 16 + (lane & 3) * 2;
    #pragma unroll
    for (int mt = 0; mt < 4; ++mt) {
        int r0 = warp_m * 64 + mt * 16 + (lane >> 2);
        #pragma unroll
        for (int half = 0; half < 2; ++half) {
            int mg = mb * 128 + r0 + half * 8;
            float bv = bias[mg];
            #pragma unroll
            for (int nt = 0; nt < 2; ++nt) {
                float v0 = acc[mt][nt][half * 2 + 0] + bv;
                float v1 = acc[mt][nt][half * 2 + 1] + bv;
                if (mode == 1) { v0 = fmaxf(v0, 0.f); v1 = fmaxf(v1, 0.f); }
                int col = colbase + nt * 8;
                if (mode == 3) {
                    outp[(size_t)(col    ) * NQ + mg] = v0;
                    outp[(size_t)(col + 1) * NQ + mg] = v1;
                } else {
                    float* dst = (mode == 1) ? &d_o1[(size_t)mg * BT + col]
                                             : &d_skip[(size_t)mg * BT + col];
                    *(float2*)dst = make_float2(v0, v1);
                }
            }
        }
    }
}

// =====================================================================
// Launch
// =====================================================================
extern "C" void kernel_launch(void* const* d_in, const int* in_sizes, int n_in,
                              void* d_out, int out_size) {
    const int*   x          = (const int*)  d_in[0];
    const float* h          = (const float*)d_in[1];
    const float* causal_w   = (const float*)d_in[2];
    const float* causal_b   = (const float*)d_in[3];
    const float* dil_sig_w  = (const float*)d_in[4];
    const float* dil_sig_b  = (const float*)d_in[5];
    const float* dil_tanh_w = (const float*)d_in[6];
    const float* dil_tanh_b = (const float*)d_in[7];
    const float* aux_sig_w  = (const float*)d_in[8];
    const float* aux_sig_b  = (const float*)d_in[9];
    const float* aux_tanh_w = (const float*)d_in[10];
    const float* aux_tanh_b = (const float*)d_in[11];
    const float* skip_w     = (const float*)d_in[12];
    const float* skip_b     = (const float*)d_in[13];
    const float* res_w      = (const float*)d_in[14];
    const float* res_b      = (const float*)d_in[15];
    const float* post1_w    = (const float*)d_in[16];
    const float* post1_b    = (const float*)d_in[17];
    const float* post2_w    = (const float*)d_in[18];
    const float* post2_b    = (const float*)d_in[19];
    const float* lin_w      = (const float*)d_in[20];
    const float* lin_b      = (const float*)d_in[21];

    cudaFuncSetAttribute(gate_k,    cudaFuncAttributeMaxDynamicSharedMemorySize, GEMM_SMEM);
    cudaFuncSetAttribute(skipres_k, cudaFuncAttributeMaxDynamicSharedMemorySize, GEMM_SMEM);
    cudaFuncSetAttribute(post_k,    cudaFuncAttributeMaxDynamicSharedMemorySize, POST_SMEM);

    {
        size_t n = PACK_TOTAL;
        pack_all_k<<<(unsigned)((n + 255) / 256), 256>>>(
            dil_sig_w, dil_tanh_w, aux_sig_w, aux_tanh_w, skip_w, res_w,
            dil_sig_b, dil_tanh_b, aux_sig_b, aux_tanh_b, skip_b, res_b,
            post1_w, post2_w, lin_w, h);
    }
    zero_skip_k<<<(NS * BT + 255) / 256, 256>>>();
    embed_k<<<dim3(BT / 256, NR), 256>>>(x, causal_w, causal_b);

    for (int l = 0; l < NLAYERS; ++l) {
        int d = 1 << (l % 10);
        int useS1 = (d < 8);
        int dn = (l + 1 < NLAYERS) ? (1 << ((l + 1) % 10)) : 0;
        if (dn >= 8) dn = 0;
        gate_k   <<<dim3(8, TT / BN, BATCH), NTHREADS, GEMM_SMEM>>>(l, d, useS1);
        skipres_k<<<dim3(6, TT / 64, BATCH), NTHREADS, GEMM_SMEM>>>(l, dn);
    }

    post_k<<<dim3(2, BT / 64), 256, POST_SMEM>>>(1, post1_b, nullptr);
    post_k<<<dim3(2, BT / 64), 256, POST_SMEM>>>(2, post2_b, nullptr);
    post_k<<<dim3(2, BT / 64), 256, POST_SMEM>>>(3, lin_b, (float*)d_out);
}

// round 16
// speedup vs baseline: 1.0895x; 1.0685x over previous
#include <cuda_runtime.h>
#include <cuda_bf16.h>
#include <math.h>
#include <stdint.h>

// ---------------- problem constants ----------------
#define BATCH   2
#define TT      4096
#define BT      8192
#define NQ      256
#define NAUX    28
#define NR      512
#define NS      256
#define NLAYERS 30

// ---------------- main GEMM tiling ----------------
#define BM 128
#define BN 128
#define NTHREADS 256
#define NSTAGES 3

// smem strides (elements)
#define SA 40        // A row: 32 k + 8 pad  (80B, conflict-free LDSM)
#define SB 136       // B row: 128 n + 8 pad (272B, conflict-free LDSM)

// ---------------- device scratch ----------------
__device__ float d_res [NR * BT];        // fp32 residual (exact accumulation)
__device__ float d_o1  [NS * BT];
__device__ float d_skip[NS * BT];

// activation bf16 hi/lo planes
__device__ __nv_bfloat16 d_resH[NR * BT], d_resL[NR * BT];
__device__ __nv_bfloat16 d_s1H [NR * BT], d_s1L [NR * BT];   // res shifted by next-layer d (d<8)
__device__ __nv_bfloat16 d_gH  [NR * BT], d_gL  [NR * BT];
__device__ __nv_bfloat16 d_hH  [32 * BT], d_hL  [32 * BT];

// weight bf16 hi/lo planes, [m][k] row-major
__device__ __nv_bfloat16 d_WgH [NLAYERS * 2 * 1024 * 512], d_WgL [NLAYERS * 2 * 1024 * 512];
__device__ __nv_bfloat16 d_WaH [NLAYERS * 1024 * 32],      d_WaL [NLAYERS * 1024 * 32];
__device__ __nv_bfloat16 d_WrsH[NLAYERS * 768 * 512],      d_WrsL[NLAYERS * 768 * 512];

__device__ float d_bg [NLAYERS * 1024];
__device__ float d_brs[NLAYERS * 768];

__device__ uint2 d_Wp12[128 * 256];
__device__ uint2 d_Wp22[128 * 256];
__device__ uint2 d_Wp32[128 * 256];

// ---------------- helpers ----------------
__device__ __forceinline__ uint32_t pk2(__nv_bfloat16 a, __nv_bfloat16 b) {
    return (uint32_t)__bfloat16_as_ushort(a) | ((uint32_t)__bfloat16_as_ushort(b) << 16);
}

__device__ __forceinline__ uint2 split2(float x, float y) {
    __nv_bfloat16 xh = __float2bfloat16_rn(x);
    __nv_bfloat16 yh = __float2bfloat16_rn(y);
    __nv_bfloat16 xl = __float2bfloat16_rn(x - __bfloat162float(xh));
    __nv_bfloat16 yl = __float2bfloat16_rn(y - __bfloat162float(yh));
    uint2 w; w.x = pk2(xh, yh); w.y = pk2(xl, yl); return w;
}

__device__ __forceinline__ void splitHL(float v, __nv_bfloat16* H, __nv_bfloat16* L, size_t o) {
    __nv_bfloat16 hh = __float2bfloat16_rn(v);
    H[o] = hh; L[o] = __float2bfloat16_rn(v - __bfloat162float(hh));
}

__device__ __forceinline__ void mma16(float* c, const uint32_t* a, const uint32_t* b) {
    asm volatile(
        "mma.sync.aligned.m16n8k16.row.col.f32.bf16.bf16.f32 "
        "{%0,%1,%2,%3}, {%4,%5,%6,%7}, {%8,%9}, {%0,%1,%2,%3};\n"
        : "+f"(c[0]), "+f"(c[1]), "+f"(c[2]), "+f"(c[3])
        : "r"(a[0]), "r"(a[1]), "r"(a[2]), "r"(a[3]), "r"(b[0]), "r"(b[1]));
}

__device__ __forceinline__ void ldm_x4(uint32_t* r, uint32_t saddr) {
    asm volatile("ldmatrix.sync.aligned.m8n8.x4.shared.b16 {%0,%1,%2,%3}, [%4];"
        : "=r"(r[0]), "=r"(r[1]), "=r"(r[2]), "=r"(r[3]) : "r"(saddr));
}
__device__ __forceinline__ void ldm_x4t(uint32_t* r, uint32_t saddr) {
    asm volatile("ldmatrix.sync.aligned.m8n8.x4.trans.shared.b16 {%0,%1,%2,%3}, [%4];"
        : "=r"(r[0]), "=r"(r[1]), "=r"(r[2]), "=r"(r[3]) : "r"(saddr));
}

__device__ __forceinline__ void cp16(void* dst, const void* src) {
    uint32_t s = (uint32_t)__cvta_generic_to_shared(dst);
    asm volatile("cp.async.cg.shared.global [%0], [%1], 16;\n" :: "r"(s), "l"(src));
}
__device__ __forceinline__ void cp16z(void* dst, const void* src, int valid) {
    uint32_t s = (uint32_t)__cvta_generic_to_shared(dst);
    asm volatile("cp.async.cg.shared.global [%0], [%1], 16, %2;\n"
                 :: "r"(s), "l"(src), "r"(valid ? 16 : 0));
}
__device__ __forceinline__ void cp_commit() {
    asm volatile("cp.async.commit_group;\n" ::: "memory");
}
__device__ __forceinline__ void cp_wait1() {
    asm volatile("cp.async.wait_group 1;\n" ::: "memory");
}
__device__ __forceinline__ void cp_wait0() {
    asm volatile("cp.async.wait_group 0;\n" ::: "memory");
}

__device__ __forceinline__ int gate_channel_of_row(int mlocal) {
    return ((mlocal >> 4) << 3) | (mlocal & 7);
}
__device__ __forceinline__ int gate_c_of_m(int m) {
    int mlocal = m & 127;
    int cc = gate_channel_of_row(mlocal & ~8);
    return (m >> 7) * 64 + cc;
}
__device__ __forceinline__ int gate_half_of_m(int m) { return (m >> 3) & 1; }

struct Stage {
    __nv_bfloat16 AH[128][SA];
    __nv_bfloat16 AL[128][SA];
    __nv_bfloat16 BH[32][SB];
    __nv_bfloat16 BL[32][SB];
};
static_assert(sizeof(Stage) == 37888, "stage size");
#define GEMM_SMEM (NSTAGES * (int)sizeof(Stage))     // 113664

// =====================================================================
// ONE merged packing kernel (weights hi/lo planes, biases, post, h)
// =====================================================================
__global__ void pack_all_k(const float* __restrict__ dsw, const float* __restrict__ dtw,
                           const float* __restrict__ asw, const float* __restrict__ atw,
                           const float* __restrict__ skw, const float* __restrict__ rew,
                           const float* __restrict__ dsb, const float* __restrict__ dtb,
                           const float* __restrict__ asb, const float* __restrict__ atb,
                           const float* __restrict__ skb, const float* __restrict__ reb,
                           const float* __restrict__ p1w, const float* __restrict__ p2w,
                           const float* __restrict__ p3w, const float* __restrict__ h) {
    size_t gi = (size_t)blockIdx.x * blockDim.x + threadIdx.x;
    const size_t N1 = (size_t)NLAYERS * 2 * 1024 * 512;
    const size_t N2 = (size_t)NLAYERS * 1024 * 32;
    const size_t N3 = (size_t)NLAYERS * 768 * 512;
    const size_t N4 = (size_t)NLAYERS * (1024 + 768);
    const size_t N5 = 3 * 128 * 256;
    const size_t N6 = (size_t)32 * BT;

    if (gi < N1) {
        int idx = (int)gi;
        int k = idx & 511, rm = idx >> 9;
        int m = rm & 1023, lt = rm >> 10;
        int tap = lt & 1, l = lt >> 1, c = gate_c_of_m(m);
        const float* src = gate_half_of_m(m) ? dtw : dsw;
        splitHL(src[((size_t)(l * NR + c) * NR + k) * 2 + tap], d_WgH, d_WgL, idx);
        return;
    }
    gi -= N1;
    if (gi < N2) {
        int idx = (int)gi;
        int k = idx & 31, rm = idx >> 5;
        int m = rm & 1023, l = rm >> 10, c = gate_c_of_m(m);
        const float* src = gate_half_of_m(m) ? atw : asw;
        splitHL((k < NAUX) ? src[(size_t)(l * NR + c) * NAUX + k] : 0.f, d_WaH, d_WaL, idx);
        return;
    }
    gi -= N2;
    if (gi < N3) {
        int idx = (int)gi;
        int k = idx & 511, rm = idx >> 9;
        int m = rm % 768, l = rm / 768;
        float v = (m < 256) ? skw[(size_t)(l * NS + m) * NR + k]
                            : rew[(size_t)(l * NR + (m - 256)) * NR + k];
        splitHL(v, d_WrsH, d_WrsL, idx);
        return;
    }
    gi -= N3;
    if (gi < N4) {
        int idx = (int)gi;
        if (idx < NLAYERS * 1024) {
            int l = idx >> 10, m = idx & 1023, c = gate_c_of_m(m);
            d_bg[idx] = gate_half_of_m(m) ? (dtb[l * NR + c] + atb[l * NR + c])
                                          : (dsb[l * NR + c] + asb[l * NR + c]);
        } else {
            int j = idx - NLAYERS * 1024;
            int l = j / 768, m = j % 768;
            d_brs[j] = (m < 256) ? skb[l * NS + m] : reb[l * NR + (m - 256)];
        }
        return;
    }
    gi -= N4;
    if (gi < N5) {
        int idx = (int)gi;
        int w = idx / 32768, r = idx % 32768;
        int k2 = r >> 8, m = r & 255;
        const float* p = (w == 0) ? p1w : (w == 1) ? p2w : p3w;
        uint2 v = split2(p[m * 256 + 2 * k2], p[m * 256 + 2 * k2 + 1]);
        if (w == 0)      d_Wp12[r] = v;
        else if (w == 1) d_Wp22[r] = v;
        else             d_Wp32[r] = v;
        return;
    }
    gi -= N5;
    if (gi < N6) {
        int idx = (int)gi;
        int a = idx / BT, j = idx % BT;
        float v = 0.f;
        if (a < NAUX) {
            int b = j >> 12, t = j & (TT - 1);
            v = h[((size_t)b * NAUX + a) * TT + t];
        }
        splitHL(v, d_hH, d_hL, idx);
    }
}
#define PACK_TOTAL ((size_t)NLAYERS*2*1024*512 + (size_t)NLAYERS*1024*32 + \
                    (size_t)NLAYERS*768*512 + (size_t)NLAYERS*(1024+768) + \
                    3*128*256 + (size_t)32*BT)

__global__ void zero_skip_k() {
    int idx = blockIdx.x * blockDim.x + threadIdx.x;
    if (idx < NS * BT) d_skip[idx] = 0.f;
}

// =====================================================================
// Embedding (table lookup) -> res fp32 + planes + s1 (layer0 d=1)
// =====================================================================
__global__ void embed_k(const int* __restrict__ x, const float* __restrict__ cw,
                        const float* __restrict__ cb) {
    int j = blockIdx.x * blockDim.x + threadIdx.x;
    int c = blockIdx.y;
    if (j >= BT) return;
    int b = j >> 12;
    int t = j & (TT - 1);
    int q1 = x[b * TT + t] & 255;
    float v = cw[(c * NQ + q1) * 2 + 1] + cb[c];
    if (t > 0) {
        int q0 = x[b * TT + t - 1] & 255;
        v += cw[(c * NQ + q0) * 2 + 0];
    }
    size_t o = (size_t)c * BT + j;
    d_res[o] = v;
    splitHL(v, d_resH, d_resL, o);
    if (t + 1 < TT) splitHL(v, d_s1H, d_s1L, o + 1);
    if (t == 0) {
        __nv_bfloat16 z = __float2bfloat16_rn(0.f);
        d_s1H[o] = z; d_s1L[o] = z;
    }
}

// =====================================================================
// Gate GEMM: M=1024, N=8192, K = 512(shift d) + 512 + 32(aux)
// 33 k32-tiles, 3-stage cp.async pipeline, one barrier/tile, occ 2.
// =====================================================================
__global__ __launch_bounds__(NTHREADS, 2)
void gate_k(int l, int d, int useS1) {
    extern __shared__ uint8_t smraw[];
    Stage* S = reinterpret_cast<Stage*>(smraw);

    int tid    = threadIdx.x;
    int lane   = tid & 31;
    int wid    = tid >> 5;
    int warp_m = wid & 1;
    int warp_n = wid >> 1;
    int mb     = blockIdx.x;
    int t0     = blockIdx.y * BN;
    int z      = blockIdx.z;

    float acc[4][4][4] = {};

    int subA  = lane >> 3;
    int rowA  = (subA & 1) * 8 + (lane & 7);
    int kbA   = (subA >> 1) * 16;
    int rowB  = lane & 15;
    int colBq = (lane >> 4) * 16;

    auto fillA = [&](int stage, int tile) {
        const __nv_bfloat16 *PH, *PL;
        int rowstride;
        if (tile < 32) {
            int tap = tile >> 4;
            int kt  = (tile & 15) * 32;
            size_t off = ((size_t)((l * 2 + tap) * 1024) + mb * 128) * 512 + kt;
            PH = d_WgH + off; PL = d_WgL + off; rowstride = 512;
        } else {
            size_t off = ((size_t)l * 1024 + mb * 128) * 32;
            PH = d_WaH + off; PL = d_WaL + off; rowstride = 32;
        }
        #pragma unroll
        for (int p = 0; p < 4; ++p) {
            int idx = tid + p * 256;
            int pl  = idx >> 9;
            int rem = idx & 511;
            int row = rem >> 2;
            int kc  = rem & 3;
            const __nv_bfloat16* src = (pl ? PL : PH) + (size_t)row * rowstride + kc * 8;
            __nv_bfloat16* dst = pl ? &S[stage].AL[row][kc * 8] : &S[stage].AH[row][kc * 8];
            cp16(dst, src);
        }
    };

    auto fillB = [&](int stage, int tile) {
        const __nv_bfloat16 *baseH, *baseL;
        int kt, doff;
        if (tile < 16) {
            baseH = useS1 ? d_s1H : d_resH;
            baseL = useS1 ? d_s1L : d_resL;
            kt = tile * 32; doff = useS1 ? 0 : d;
        } else if (tile < 32) {
            baseH = d_resH; baseL = d_resL; kt = (tile - 16) * 32; doff = 0;
        } else {
            baseH = d_hH; baseL = d_hL; kt = 0; doff = 0;
        }
        #pragma unroll
        for (int p = 0; p < 4; ++p) {
            int idx = tid + p * 256;
            int pl  = idx >> 9;
            int rem = idx & 511;
            int row = rem >> 4;
            int c16 = rem & 15;
            int col = t0 + c16 * 8 - doff;
            const __nv_bfloat16* bp = pl ? baseL : baseH;
            const __nv_bfloat16* src = bp + (size_t)(kt + row) * BT + (size_t)z * TT
                                          + (col >= 0 ? col : 0);
            __nv_bfloat16* dst = pl ? &S[stage].BL[row][c16 * 8] : &S[stage].BH[row][c16 * 8];
            cp16z(dst, src, col >= 0);
        }
    };

    auto compute = [&](int stage) {
        uint32_t aH = (uint32_t)__cvta_generic_to_shared(&S[stage].AH[0][0]);
        uint32_t aL = (uint32_t)__cvta_generic_to_shared(&S[stage].AL[0][0]);
        uint32_t bH = (uint32_t)__cvta_generic_to_shared(&S[stage].BH[0][0]);
        uint32_t bL = (uint32_t)__cvta_generic_to_shared(&S[stage].BL[0][0]);
        #pragma unroll
        for (int k16 = 0; k16 < 2; ++k16) {
            uint32_t bfH[2][4], bfL[2][4];
            #pragma unroll
            for (int hh = 0; hh < 2; ++hh) {
                uint32_t boff = (uint32_t)((k16 * 16 + rowB) * (SB * 2)
                                           + warp_n * 64 + hh * 32 + colBq);
                ldm_x4t(bfH[hh], bH + boff);
                ldm_x4t(bfL[hh], bL + boff);
            }
            #pragma unroll
            for (int mt = 0; mt < 4; ++mt) {
                uint32_t afH[4], afL[4];
                uint32_t off = (uint32_t)((warp_m * 64 + mt * 16 + rowA) * (SA * 2)
                                          + k16 * 32 + kbA);
                ldm_x4(afH, aH + off);
                ldm_x4(afL, aL + off);
                #pragma unroll
                for (int nt = 0; nt < 4; ++nt)
                    mma16(acc[mt][nt], afH, bfH[nt >> 1] + (nt & 1) * 2);
                #pragma unroll
                for (int nt = 0; nt < 4; ++nt)
                    mma16(acc[mt][nt], afH, bfL[nt >> 1] + (nt & 1) * 2);
                #pragma unroll
                for (int nt = 0; nt < 4; ++nt)
                    mma16(acc[mt][nt], afL, bfH[nt >> 1] + (nt & 1) * 2);
            }
        }
    };

    const int NT = 33;
    fillA(0, 0); fillB(0, 0); cp_commit();
    fillA(1, 1); fillB(1, 1); cp_commit();
    for (int t = 0; t < NT; ++t) {
        if (t + 1 < NT) cp_wait1(); else cp_wait0();
        __syncthreads();
        if (t + 2 < NT) {
            int s2 = (t + 2) % 3;
            fillA(s2, t + 2); fillB(s2, t + 2); cp_commit();
        }
        compute(t % 3);
    }

    // gated activation epilogue -> g planes
    const float* bgp = d_bg + l * 1024 + mb * 128;
    int colbase = z * TT + t0 + warp_n * 32 + (lane & 3) * 2;
    #pragma unroll
    for (int mt = 0; mt < 4; ++mt) {
        int r  = warp_m * 64 + mt * 16 + (lane >> 2);
        int cc = gate_channel_of_row(r);
        int cg = mb * 64 + cc;
        float bs = bgp[r];
        float bt = bgp[r + 8];
        #pragma unroll
        for (int nt = 0; nt < 4; ++nt) {
            float s0  = acc[mt][nt][0] + bs;
            float s1  = acc[mt][nt][1] + bs;
            float tv0 = acc[mt][nt][2] + bt;
            float tv1 = acc[mt][nt][3] + bt;
            float g0 = __fdividef(1.f, 1.f + __expf(-s0)) *
                       (1.f - __fdividef(2.f, __expf(2.f * tv0) + 1.f));
            float g1 = __fdividef(1.f, 1.f + __expf(-s1)) *
                       (1.f - __fdividef(2.f, __expf(2.f * tv1) + 1.f));
            uint2 w = split2(g0, g1);
            size_t o = (size_t)cg * BT + colbase + nt * 8;
            *(uint32_t*)&d_gH[o] = w.x;
            *(uint32_t*)&d_gL[o] = w.y;
        }
    }
}

// =====================================================================
// Skip/Res GEMM: M=768 (BM=128, 6 m-blocks), K=512; RMW epilogue
// + writes next layer's shifted planes (dnext in {1,2,4}, else 0)
// =====================================================================
__global__ __launch_bounds__(NTHREADS, 2)
void skipres_k(int l, int dnext) {
    extern __shared__ uint8_t smraw[];
    Stage* S = reinterpret_cast<Stage*>(smraw);

    int tid    = threadIdx.x;
    int lane   = tid & 31;
    int wid    = tid >> 5;
    int warp_m = wid & 1;
    int warp_n = wid >> 1;
    int mb     = blockIdx.x;        // 0..5
    int t0     = blockIdx.y * BN;
    int z      = blockIdx.z;

    float acc[4][4][4] = {};

    int subA  = lane >> 3;
    int rowA  = (subA & 1) * 8 + (lane & 7);
    int kbA   = (subA >> 1) * 16;
    int rowB  = lane & 15;
    int colBq = (lane >> 4) * 16;

    size_t aoff = ((size_t)l * 768 + mb * 128) * 512;

    auto fillA = [&](int stage, int tile) {
        int kt = tile * 32;
        #pragma unroll
        for (int p = 0; p < 4; ++p) {
            int idx = tid + p * 256;
            int pl  = idx >> 9;
            int rem = idx & 511;
            int row = rem >> 2;
            int kc  = rem & 3;
            const __nv_bfloat16* src = (pl ? d_WrsL : d_WrsH) + aoff
                                        + (size_t)row * 512 + kt + kc * 8;
            __nv_bfloat16* dst = pl ? &S[stage].AL[row][kc * 8] : &S[stage].AH[row][kc * 8];
            cp16(dst, src);
        }
    };
    auto fillB = [&](int stage, int tile) {
        int kt = tile * 32;
        #pragma unroll
        for (int p = 0; p < 4; ++p) {
            int idx = tid + p * 256;
            int pl  = idx >> 9;
            int rem = idx & 511;
            int row = rem >> 4;
            int c16 = rem & 15;
            const __nv_bfloat16* bp = pl ? d_gL : d_gH;
            const __nv_bfloat16* src = bp + (size_t)(kt + row) * BT + (size_t)z * TT
                                          + t0 + c16 * 8;
            __nv_bfloat16* dst = pl ? &S[stage].BL[row][c16 * 8] : &S[stage].BH[row][c16 * 8];
            cp16(dst, src);
        }
    };
    auto compute = [&](int stage) {
        uint32_t aH = (uint32_t)__cvta_generic_to_shared(&S[stage].AH[0][0]);
        uint32_t aL = (uint32_t)__cvta_generic_to_shared(&S[stage].AL[0][0]);
        uint32_t bH = (uint32_t)__cvta_generic_to_shared(&S[stage].BH[0][0]);
        uint32_t bL = (uint32_t)__cvta_generic_to_shared(&S[stage].BL[0][0]);
        #pragma unroll
        for (int k16 = 0; k16 < 2; ++k16) {
            uint32_t bfH[2][4], bfL[2][4];
            #pragma unroll
            for (int hh = 0; hh < 2; ++hh) {
                uint32_t boff = (uint32_t)((k16 * 16 + rowB) * (SB * 2)
                                           + warp_n * 64 + hh * 32 + colBq);
                ldm_x4t(bfH[hh], bH + boff);
                ldm_x4t(bfL[hh], bL + boff);
            }
            #pragma unroll
            for (int mt = 0; mt < 4; ++mt) {
                uint32_t afH[4], afL[4];
                uint32_t off = (uint32_t)((warp_m * 64 + mt * 16 + rowA) * (SA * 2)
                                          + k16 * 32 + kbA);
                ldm_x4(afH, aH + off);
                ldm_x4(afL, aL + off);
                #pragma unroll
                for (int nt = 0; nt < 4; ++nt)
                    mma16(acc[mt][nt], afH, bfH[nt >> 1] + (nt & 1) * 2);
                #pragma unroll
                for (int nt = 0; nt < 4; ++nt)
                    mma16(acc[mt][nt], afH, bfL[nt >> 1] + (nt & 1) * 2);
                #pragma unroll
                for (int nt = 0; nt < 4; ++nt)
                    mma16(acc[mt][nt], afL, bfH[nt >> 1] + (nt & 1) * 2);
            }
        }
    };

    const int NT = 16;
    fillA(0, 0); fillB(0, 0); cp_commit();
    fillA(1, 1); fillB(1, 1); cp_commit();
    for (int t = 0; t < NT; ++t) {
        if (t + 1 < NT) cp_wait1(); else cp_wait0();
        __syncthreads();
        if (t + 2 < NT) {
            int s2 = (t + 2) % 3;
            fillA(s2, t + 2); fillB(s2, t + 2); cp_commit();
        }
        compute(t % 3);
    }

    int colbase = z * TT + t0 + warp_n * 32 + (lane & 3) * 2;
    #pragma unroll
    for (int mt = 0; mt < 4; ++mt) {
        int r0 = warp_m * 64 + mt * 16 + (lane >> 2);
        #pragma unroll
        for (int half = 0; half < 2; ++half) {
            int mg = mb * 128 + r0 + half * 8;
            float bias = d_brs[l * 768 + mg];
            #pragma unroll
            for (int nt = 0; nt < 4; ++nt) {
                int col = colbase + nt * 8;
                if (mg < 256) {
                    float* dst = &d_skip[(size_t)mg * BT + col];
                    float2 v = *(float2*)dst;
                    v.x += acc[mt][nt][half * 2 + 0] + bias;
                    v.y += acc[mt][nt][half * 2 + 1] + bias;
                    *(float2*)dst = v;
                } else {
                    int ch = mg - 256;
                    float* dst = &d_res[(size_t)ch * BT + col];
                    float2 v = *(float2*)dst;
                    v.x += acc[mt][nt][half * 2 + 0] + bias;
                    v.y += acc[mt][nt][half * 2 + 1] + bias;
                    *(float2*)dst = v;
                    uint2 w = split2(v.x, v.y);
                    size_t o = (size_t)ch * BT + col;
                    *(uint32_t*)&d_resH[o] = w.x;
                    *(uint32_t*)&d_resL[o] = w.y;
                    if (dnext) {
                        int tl = col - z * TT;
                        if (tl + dnext < TT)     splitHL(v.x, d_s1H, d_s1L, o + dnext);
                        if (tl + 1 + dnext < TT) splitHL(v.y, d_s1H, d_s1L, o + 1 + dnext);
                        __nv_bfloat16 zb = __float2bfloat16_rn(0.f);
                        if (tl < dnext)     { d_s1H[o] = zb;     d_s1L[o] = zb; }
                        if (tl + 1 < dnext) { d_s1H[o + 1] = zb; d_s1L[o + 1] = zb; }
                    }
                }
            }
        }
    }
}

// =====================================================================
// Post GEMMs (register-split path): M=256, N=8192, K=256
// =====================================================================
struct PostTiles {
    uint2 A[2][16][132];
    uint2 B[2][16][68];
};
#define POST_SMEM ((int)sizeof(PostTiles))

__device__ __forceinline__ void post_sts(PostTiles& S, int buf, int tid,
                                         const uint4* ra, float4 rb0, float4 rb1) {
    #pragma unroll
    for (int p = 0; p < 4; ++p) {
        int e  = tid + p * 256;
        int k2 = e >> 6;
        int m2 = (e & 63) << 1;
        *(uint4*)&S.A[buf][k2][m2] = ra[p];
    }
    int k2 = tid >> 4;
    int n4 = (tid & 15) << 2;
    const float* x0 = &rb0.x;
    const float* x1 = &rb1.x;
    #pragma unroll
    for (int j = 0; j < 4; ++j)
        S.B[buf][k2][n4 + j] = split2(x0[j], x1[j]);
}

#define POST_MMA3(acc, Ab, Bb, wm, wn, lane_)                                   \
    do {                                                                        \
        int c_ = (lane_) & 3, q_ = (lane_) >> 2;                                \
        _Pragma("unroll")                                                       \
        for (int ksb = 0; ksb < 2; ++ksb) {                                     \
            uint2 bw[2][2];                                                     \
            _Pragma("unroll")                                                   \
            for (int nt = 0; nt < 2; ++nt) {                                    \
                bw[nt][0] = (Bb)[ksb * 8 + c_][(wn) * 16 + nt * 8 + q_];        \
                bw[nt][1] = (Bb)[ksb * 8 + c_ + 4][(wn) * 16 + nt * 8 + q_];    \
            }                                                                   \
            _Pragma("unroll")                                                   \
            for (int mt = 0; mt < 4; ++mt) {                                    \
                int r_ = (wm) * 64 + mt * 16 + q_;                              \
                uint2 a0 = (Ab)[ksb * 8 + c_][r_];                              \
                uint2 a1 = (Ab)[ksb * 8 + c_][r_ + 8];                          \
                uint2 a2 = (Ab)[ksb * 8 + c_ + 4][r_];                          \
                uint2 a3 = (Ab)[ksb * 8 + c_ + 4][r_ + 8];                      \
                uint32_t ah_[4] = {a0.x, a1.x, a2.x, a3.x};                     \
                uint32_t al_[4] = {a0.y, a1.y, a2.y, a3.y};                     \
                uint32_t bh0_[2] = {bw[0][0].x, bw[0][1].x};                    \
                uint32_t bh1_[2] = {bw[1][0].x, bw[1][1].x};                    \
                uint32_t bl0_[2] = {bw[0][0].y, bw[0][1].y};                    \
                uint32_t bl1_[2] = {bw[1][0].y, bw[1][1].y};                    \
                mma16(acc[mt][0], ah_, bh0_);                                   \
                mma16(acc[mt][1], ah_, bh1_);                                   \
                mma16(acc[mt][0], ah_, bl0_);                                   \
                mma16(acc[mt][1], ah_, bl1_);                                   \
                mma16(acc[mt][0], al_, bh0_);                                   \
                mma16(acc[mt][1], al_, bh1_);                                   \
            }                                                                   \
        }                                                                       \
    } while (0)

__global__ __launch_bounds__(256, 2)
void post_k(int mode, const float* __restrict__ bias, float* __restrict__ outp) {
    extern __shared__ uint8_t smraw[];
    PostTiles& S = *reinterpret_cast<PostTiles*>(smraw);

    int tid    = threadIdx.x;
    int lane   = tid & 31;
    int wid    = tid >> 5;
    int warp_m = wid & 1;
    int warp_n = wid >> 1;
    int mb     = blockIdx.x;
    int j0     = blockIdx.y * 64;

    const uint2* A    = (mode == 1) ? d_Wp12 : (mode == 2) ? d_Wp22 : d_Wp32;
    const float* Bsrc = (mode == 2) ? d_o1 : d_skip;

    float acc[4][2][4] = {};
    uint4  ra[4];
    float4 rb0, rb1;

    auto FETCH = [&](int tile) {
        #pragma unroll
        for (int p = 0; p < 4; ++p) {
            int e  = tid + p * 256;
            int k2 = e >> 6;
            int m2 = (e & 63) << 1;
            ra[p] = *(const uint4*)&A[(size_t)(tile * 16 + k2) * 256 + mb * 128 + m2];
        }
        int k2 = tid >> 4;
        int n4 = (tid & 15) << 2;
        int k0 = tile * 32 + 2 * k2;
        rb0 = *(const float4*)&Bsrc[(size_t)k0 * BT + j0 + n4];
        rb1 = *(const float4*)&Bsrc[(size_t)(k0 + 1) * BT + j0 + n4];
        if (mode == 1) {
            rb0.x = fmaxf(rb0.x, 0.f); rb0.y = fmaxf(rb0.y, 0.f);
            rb0.z = fmaxf(rb0.z, 0.f); rb0.w = fmaxf(rb0.w, 0.f);
            rb1.x = fmaxf(rb1.x, 0.f); rb1.y = fmaxf(rb1.y, 0.f);
            rb1.z = fmaxf(rb1.z, 0.f); rb1.w = fmaxf(rb1.w, 0.f);
        }
    };

    FETCH(0);
    post_sts(S, 0, tid, ra, rb0, rb1);
    __syncthreads();

    const int NT = 8;
    for (int t = 0; t < NT; ++t) {
        if (t + 1 < NT) FETCH(t + 1);
        POST_MMA3(acc, S.A[t & 1], S.B[t & 1], warp_m, warp_n, lane);
        if (t + 1 < NT) post_sts(S, (t + 1) & 1, tid, ra, rb0, rb1);
        __syncthreads();
    }

    int colbase = j0 + warp_n * 16 + (lane & 3) * 2;
    #pragma unroll
    for (int mt = 0; mt < 4; ++mt) {
        int r0 = warp_m * 64 + mt * 16 + (lane >> 2);
        #pragma unroll
        for (int half = 0; half < 2; ++half) {
            int mg = mb * 128 + r0 + half * 8;
            float bv = bias[mg];
            #pragma unroll
            for (int nt = 0; nt < 2; ++nt) {
                float v0 = acc[mt][nt][half * 2 + 0] + bv;
                float v1 = acc[mt][nt][half * 2 + 1] + bv;
                if (mode == 1) { v0 = fmaxf(v0, 0.f); v1 = fmaxf(v1, 0.f); }
                int col = colbase + nt * 8;
                if (mode == 3) {
                    outp[(size_t)(col    ) * NQ + mg] = v0;
                    outp[(size_t)(col + 1) * NQ + mg] = v1;
                } else {
                    float* dst = (mode == 1) ? &d_o1[(size_t)mg * BT + col]
                                             : &d_skip[(size_t)mg * BT + col];
                    *(float2*)dst = make_float2(v0, v1);
                }
            }
        }
    }
}

// =====================================================================
// Launch
// =====================================================================
extern "C" void kernel_launch(void* const* d_in, const int* in_sizes, int n_in,
                              void* d_out, int out_size) {
    const int*   x          = (const int*)  d_in[0];
    const float* h          = (const float*)d_in[1];
    const float* causal_w   = (const float*)d_in[2];
    const float* causal_b   = (const float*)d_in[3];
    const float* dil_sig_w  = (const float*)d_in[4];
    const float* dil_sig_b  = (const float*)d_in[5];
    const float* dil_tanh_w = (const float*)d_in[6];
    const float* dil_tanh_b = (const float*)d_in[7];
    const float* aux_sig_w  = (const float*)d_in[8];
    const float* aux_sig_b  = (const float*)d_in[9];
    const float* aux_tanh_w = (const float*)d_in[10];
    const float* aux_tanh_b = (const float*)d_in[11];
    const float* skip_w     = (const float*)d_in[12];
    const float* skip_b     = (const float*)d_in[13];
    const float* res_w      = (const float*)d_in[14];
    const float* res_b      = (const float*)d_in[15];
    const float* post1_w    = (const float*)d_in[16];
    const float* post1_b    = (const float*)d_in[17];
    const float* post2_w    = (const float*)d_in[18];
    const float* post2_b    = (const float*)d_in[19];
    const float* lin_w      = (const float*)d_in[20];
    const float* lin_b      = (const float*)d_in[21];

    cudaFuncSetAttribute(gate_k,    cudaFuncAttributeMaxDynamicSharedMemorySize, GEMM_SMEM);
    cudaFuncSetAttribute(skipres_k, cudaFuncAttributeMaxDynamicSharedMemorySize, GEMM_SMEM);
    cudaFuncSetAttribute(post_k,    cudaFuncAttributeMaxDynamicSharedMemorySize, POST_SMEM);

    {
        size_t n = PACK_TOTAL;
        pack_all_k<<<(unsigned)((n + 255) / 256), 256>>>(
            dil_sig_w, dil_tanh_w, aux_sig_w, aux_tanh_w, skip_w, res_w,
            dil_sig_b, dil_tanh_b, aux_sig_b, aux_tanh_b, skip_b, res_b,
            post1_w, post2_w, lin_w, h);
    }
    zero_skip_k<<<(NS * BT + 255) / 256, 256>>>();
    embed_k<<<dim3(BT / 256, NR), 256>>>(x, causal_w, causal_b);

    for (int l = 0; l < NLAYERS; ++l) {
        int d = 1 << (l % 10);
        int useS1 = (d < 8);
        int dn = (l + 1 < NLAYERS) ? (1 << ((l + 1) % 10)) : 0;
        if (dn >= 8) dn = 0;
        gate_k   <<<dim3(8, TT / BN, BATCH), NTHREADS, GEMM_SMEM>>>(l, d, useS1);
        skipres_k<<<dim3(6, TT / BN, BATCH), NTHREADS, GEMM_SMEM>>>(l, dn);
    }

    post_k<<<dim3(2, BT / 64), 256, POST_SMEM>>>(1, post1_b, nullptr);
    post_k<<<dim3(2, BT / 64), 256, POST_SMEM>>>(2, post2_b, nullptr);
    post_k<<<dim3(2, BT / 64), 256, POST_SMEM>>>(3, lin_b, (float*)d_out);
}

// round 17
// speedup vs baseline: 1.2086x; 1.1094x over previous
#include <cuda_runtime.h>
#include <cuda_bf16.h>
#include <math.h>
#include <stdint.h>

// ---------------- problem constants ----------------
#define BATCH   2
#define TT      4096
#define BT      8192
#define NQ      256
#define NAUX    28
#define NR      512
#define NS      256
#define NLAYERS 30

// ---------------- main GEMM tiling ----------------
#define BM 128
#define BN 128
#define NTHREADS 256
#define NSTAGES 3

// smem strides (elements)
#define SA 40        // A row: 32 k + 8 pad
#define SB 136       // B row: 128 n + 8 pad

#define PLANE ((size_t)NR * BT)

// ---------------- device scratch ----------------
__device__ float d_res [NR * BT];        // fp32 residual (exact accumulation)
__device__ float d_o1  [NS * BT];
__device__ float d_skip[NS * BT];
__device__ int   d_cnt [64];             // per-(t0,z) gate completion counters

// activation bf16 hi/lo planes, PING-PONG buffered by layer parity
__device__ __nv_bfloat16 d_resH[2 * NR * BT], d_resL[2 * NR * BT];
__device__ __nv_bfloat16 d_s1H [2 * NR * BT], d_s1L [2 * NR * BT];
__device__ __nv_bfloat16 d_gH  [NR * BT],     d_gL  [NR * BT];
__device__ __nv_bfloat16 d_hH  [32 * BT],     d_hL  [32 * BT];

// weight bf16 hi/lo planes, [m][k] row-major
__device__ __nv_bfloat16 d_WgH [NLAYERS * 2 * 1024 * 512], d_WgL [NLAYERS * 2 * 1024 * 512];
__device__ __nv_bfloat16 d_WaH [NLAYERS * 1024 * 32],      d_WaL [NLAYERS * 1024 * 32];
__device__ __nv_bfloat16 d_WrsH[NLAYERS * 768 * 512],      d_WrsL[NLAYERS * 768 * 512];

__device__ float d_bg [NLAYERS * 1024];
__device__ float d_brs[NLAYERS * 768];

__device__ uint2 d_Wp12[128 * 256];
__device__ uint2 d_Wp22[128 * 256];
__device__ uint2 d_Wp32[128 * 256];

// ---------------- helpers ----------------
__device__ __forceinline__ uint32_t pk2(__nv_bfloat16 a, __nv_bfloat16 b) {
    return (uint32_t)__bfloat16_as_ushort(a) | ((uint32_t)__bfloat16_as_ushort(b) << 16);
}

__device__ __forceinline__ uint2 split2(float x, float y) {
    __nv_bfloat16 xh = __float2bfloat16_rn(x);
    __nv_bfloat16 yh = __float2bfloat16_rn(y);
    __nv_bfloat16 xl = __float2bfloat16_rn(x - __bfloat162float(xh));
    __nv_bfloat16 yl = __float2bfloat16_rn(y - __bfloat162float(yh));
    uint2 w; w.x = pk2(xh, yh); w.y = pk2(xl, yl); return w;
}

__device__ __forceinline__ void splitHL(float v, __nv_bfloat16* H, __nv_bfloat16* L, size_t o) {
    __nv_bfloat16 hh = __float2bfloat16_rn(v);
    H[o] = hh; L[o] = __float2bfloat16_rn(v - __bfloat162float(hh));
}

__device__ __forceinline__ void mma16(float* c, const uint32_t* a, const uint32_t* b) {
    asm volatile(
        "mma.sync.aligned.m16n8k16.row.col.f32.bf16.bf16.f32 "
        "{%0,%1,%2,%3}, {%4,%5,%6,%7}, {%8,%9}, {%0,%1,%2,%3};\n"
        : "+f"(c[0]), "+f"(c[1]), "+f"(c[2]), "+f"(c[3])
        : "r"(a[0]), "r"(a[1]), "r"(a[2]), "r"(a[3]), "r"(b[0]), "r"(b[1]));
}

__device__ __forceinline__ void ldm_x4(uint32_t* r, uint32_t saddr) {
    asm volatile("ldmatrix.sync.aligned.m8n8.x4.shared.b16 {%0,%1,%2,%3}, [%4];"
        : "=r"(r[0]), "=r"(r[1]), "=r"(r[2]), "=r"(r[3]) : "r"(saddr));
}
__device__ __forceinline__ void ldm_x4t(uint32_t* r, uint32_t saddr) {
    asm volatile("ldmatrix.sync.aligned.m8n8.x4.trans.shared.b16 {%0,%1,%2,%3}, [%4];"
        : "=r"(r[0]), "=r"(r[1]), "=r"(r[2]), "=r"(r[3]) : "r"(saddr));
}

__device__ __forceinline__ void cp16(void* dst, const void* src) {
    uint32_t s = (uint32_t)__cvta_generic_to_shared(dst);
    asm volatile("cp.async.cg.shared.global [%0], [%1], 16;\n" :: "r"(s), "l"(src));
}
__device__ __forceinline__ void cp16z(void* dst, const void* src, int valid) {
    uint32_t s = (uint32_t)__cvta_generic_to_shared(dst);
    asm volatile("cp.async.cg.shared.global [%0], [%1], 16, %2;\n"
                 :: "r"(s), "l"(src), "r"(valid ? 16 : 0));
}
__device__ __forceinline__ void cp_commit() {
    asm volatile("cp.async.commit_group;\n" ::: "memory");
}
__device__ __forceinline__ void cp_wait1() {
    asm volatile("cp.async.wait_group 1;\n" ::: "memory");
}
__device__ __forceinline__ void cp_wait0() {
    asm volatile("cp.async.wait_group 0;\n" ::: "memory");
}

__device__ __forceinline__ int ld_acq(const int* p) {
    int v;
    asm volatile("ld.global.acquire.gpu.b32 %0, [%1];" : "=r"(v) : "l"(p) : "memory");
    return v;
}

__device__ __forceinline__ int gate_channel_of_row(int mlocal) {
    return ((mlocal >> 4) << 3) | (mlocal & 7);
}
__device__ __forceinline__ int gate_c_of_m(int m) {
    int mlocal = m & 127;
    int cc = gate_channel_of_row(mlocal & ~8);
    return (m >> 7) * 64 + cc;
}
__device__ __forceinline__ int gate_half_of_m(int m) { return (m >> 3) & 1; }

struct Stage {
    __nv_bfloat16 AH[128][SA];
    __nv_bfloat16 AL[128][SA];
    __nv_bfloat16 BH[32][SB];
    __nv_bfloat16 BL[32][SB];
};
static_assert(sizeof(Stage) == 37888, "stage size");
#define GEMM_SMEM (NSTAGES * (int)sizeof(Stage))     // 113664

// =====================================================================
// ONE merged packing kernel
// =====================================================================
__global__ void pack_all_k(const float* __restrict__ dsw, const float* __restrict__ dtw,
                           const float* __restrict__ asw, const float* __restrict__ atw,
                           const float* __restrict__ skw, const float* __restrict__ rew,
                           const float* __restrict__ dsb, const float* __restrict__ dtb,
                           const float* __restrict__ asb, const float* __restrict__ atb,
                           const float* __restrict__ skb, const float* __restrict__ reb,
                           const float* __restrict__ p1w, const float* __restrict__ p2w,
                           const float* __restrict__ p3w, const float* __restrict__ h) {
    size_t gi = (size_t)blockIdx.x * blockDim.x + threadIdx.x;
    const size_t N1 = (size_t)NLAYERS * 2 * 1024 * 512;
    const size_t N2 = (size_t)NLAYERS * 1024 * 32;
    const size_t N3 = (size_t)NLAYERS * 768 * 512;
    const size_t N4 = (size_t)NLAYERS * (1024 + 768);
    const size_t N5 = 3 * 128 * 256;
    const size_t N6 = (size_t)32 * BT;

    if (gi < N1) {
        int idx = (int)gi;
        int k = idx & 511, rm = idx >> 9;
        int m = rm & 1023, lt = rm >> 10;
        int tap = lt & 1, l = lt >> 1, c = gate_c_of_m(m);
        const float* src = gate_half_of_m(m) ? dtw : dsw;
        splitHL(src[((size_t)(l * NR + c) * NR + k) * 2 + tap], d_WgH, d_WgL, idx);
        return;
    }
    gi -= N1;
    if (gi < N2) {
        int idx = (int)gi;
        int k = idx & 31, rm = idx >> 5;
        int m = rm & 1023, l = rm >> 10, c = gate_c_of_m(m);
        const float* src = gate_half_of_m(m) ? atw : asw;
        splitHL((k < NAUX) ? src[(size_t)(l * NR + c) * NAUX + k] : 0.f, d_WaH, d_WaL, idx);
        return;
    }
    gi -= N2;
    if (gi < N3) {
        int idx = (int)gi;
        int k = idx & 511, rm = idx >> 9;
        int m = rm % 768, l = rm / 768;
        float v = (m < 256) ? skw[(size_t)(l * NS + m) * NR + k]
                            : rew[(size_t)(l * NR + (m - 256)) * NR + k];
        splitHL(v, d_WrsH, d_WrsL, idx);
        return;
    }
    gi -= N3;
    if (gi < N4) {
        int idx = (int)gi;
        if (idx < NLAYERS * 1024) {
            int l = idx >> 10, m = idx & 1023, c = gate_c_of_m(m);
            d_bg[idx] = gate_half_of_m(m) ? (dtb[l * NR + c] + atb[l * NR + c])
                                          : (dsb[l * NR + c] + asb[l * NR + c]);
        } else {
            int j = idx - NLAYERS * 1024;
            int l = j / 768, m = j % 768;
            d_brs[j] = (m < 256) ? skb[l * NS + m] : reb[l * NR + (m - 256)];
        }
        return;
    }
    gi -= N4;
    if (gi < N5) {
        int idx = (int)gi;
        int w = idx / 32768, r = idx % 32768;
        int k2 = r >> 8, m = r & 255;
        const float* p = (w == 0) ? p1w : (w == 1) ? p2w : p3w;
        uint2 v = split2(p[m * 256 + 2 * k2], p[m * 256 + 2 * k2 + 1]);
        if (w == 0)      d_Wp12[r] = v;
        else if (w == 1) d_Wp22[r] = v;
        else             d_Wp32[r] = v;
        return;
    }
    gi -= N5;
    if (gi < N6) {
        int idx = (int)gi;
        int a = idx / BT, j = idx % BT;
        float v = 0.f;
        if (a < NAUX) {
            int b = j >> 12, t = j & (TT - 1);
            v = h[((size_t)b * NAUX + a) * TT + t];
        }
        splitHL(v, d_hH, d_hL, idx);
    }
}
#define PACK_TOTAL ((size_t)NLAYERS*2*1024*512 + (size_t)NLAYERS*1024*32 + \
                    (size_t)NLAYERS*768*512 + (size_t)NLAYERS*(1024+768) + \
                    3*128*256 + (size_t)32*BT)

__global__ void zero_skip_k() {
    int idx = blockIdx.x * blockDim.x + threadIdx.x;
    if (idx < NS * BT) d_skip[idx] = 0.f;
    if (idx < 64) d_cnt[idx] = 0;
}

// =====================================================================
// Embedding (table lookup) -> res fp32 + planes buf0 + s1 buf0 (layer0 d=1)
// =====================================================================
__global__ void embed_k(const int* __restrict__ x, const float* __restrict__ cw,
                        const float* __restrict__ cb) {
    int j = blockIdx.x * blockDim.x + threadIdx.x;
    int c = blockIdx.y;
    if (j >= BT) return;
    int b = j >> 12;
    int t = j & (TT - 1);
    int q1 = x[b * TT + t] & 255;
    float v = cw[(c * NQ + q1) * 2 + 1] + cb[c];
    if (t > 0) {
        int q0 = x[b * TT + t - 1] & 255;
        v += cw[(c * NQ + q0) * 2 + 0];
    }
    size_t o = (size_t)c * BT + j;
    d_res[o] = v;
    splitHL(v, d_resH, d_resL, o);
    if (t + 1 < TT) splitHL(v, d_s1H, d_s1L, o + 1);
    if (t == 0) {
        __nv_bfloat16 z = __float2bfloat16_rn(0.f);
        d_s1H[o] = z; d_s1L[o] = z;
    }
}

// =====================================================================
// FUSED layer kernel: bid<512 = gate tile, bid>=512 = skipres tile.
// skipres(t0,z) acquire-spins on d_cnt[z*32+t0b] == 8*(l+1).
// res/s1 planes ping-pong by layer parity (gate reads rp, skipres writes wp).
// =====================================================================
__global__ __launch_bounds__(NTHREADS, 2)
void layer_k(int l, int dd, int useS1, int dnext) {
    extern __shared__ uint8_t smraw[];
    Stage* S = reinterpret_cast<Stage*>(smraw);

    int tid    = threadIdx.x;
    int lane   = tid & 31;
    int wid    = tid >> 5;
    int warp_m = wid & 1;
    int warp_n = wid >> 1;
    int bid    = blockIdx.x;

    int rp = l & 1;
    int wp = rp ^ 1;

    int subA  = lane >> 3;
    int rowA  = (subA & 1) * 8 + (lane & 7);
    int kbA   = (subA >> 1) * 16;
    int rowB  = lane & 15;
    int colBq = (lane >> 4) * 16;

    if (bid < 512) {
        // ================= GATE tile =================
        int mb  = bid & 7;
        int tyb = (bid >> 3) & 31;
        int z   = bid >> 8;
        int t0  = tyb * BN;

        float acc[4][4][4] = {};

        auto fillA = [&](int stage, int tile) {
            const __nv_bfloat16 *PH, *PL;
            int rowstride;
            if (tile < 32) {
                int tap = tile >> 4;
                int kt  = (tile & 15) * 32;
                size_t off = ((size_t)((l * 2 + tap) * 1024) + mb * 128) * 512 + kt;
                PH = d_WgH + off; PL = d_WgL + off; rowstride = 512;
            } else {
                size_t off = ((size_t)l * 1024 + mb * 128) * 32;
                PH = d_WaH + off; PL = d_WaL + off; rowstride = 32;
            }
            #pragma unroll
            for (int p = 0; p < 4; ++p) {
                int idx = tid + p * 256;
                int pl  = idx >> 9;
                int rem = idx & 511;
                int row = rem >> 2;
                int kc  = rem & 3;
                const __nv_bfloat16* src = (pl ? PL : PH) + (size_t)row * rowstride + kc * 8;
                __nv_bfloat16* dst = pl ? &S[stage].AL[row][kc * 8] : &S[stage].AH[row][kc * 8];
                cp16(dst, src);
            }
        };

        auto fillB = [&](int stage, int tile) {
            const __nv_bfloat16 *baseH, *baseL;
            int kt, doff;
            if (tile < 16) {
                baseH = (useS1 ? d_s1H : d_resH) + (size_t)rp * PLANE;
                baseL = (useS1 ? d_s1L : d_resL) + (size_t)rp * PLANE;
                kt = tile * 32; doff = useS1 ? 0 : dd;
            } else if (tile < 32) {
                baseH = d_resH + (size_t)rp * PLANE;
                baseL = d_resL + (size_t)rp * PLANE;
                kt = (tile - 16) * 32; doff = 0;
            } else {
                baseH = d_hH; baseL = d_hL; kt = 0; doff = 0;
            }
            #pragma unroll
            for (int p = 0; p < 4; ++p) {
                int idx = tid + p * 256;
                int pl  = idx >> 9;
                int rem = idx & 511;
                int row = rem >> 4;
                int c16 = rem & 15;
                int col = t0 + c16 * 8 - doff;
                const __nv_bfloat16* bp = pl ? baseL : baseH;
                const __nv_bfloat16* src = bp + (size_t)(kt + row) * BT + (size_t)z * TT
                                              + (col >= 0 ? col : 0);
                __nv_bfloat16* dst = pl ? &S[stage].BL[row][c16 * 8] : &S[stage].BH[row][c16 * 8];
                cp16z(dst, src, col >= 0);
            }
        };

        auto compute = [&](int stage) {
            uint32_t aH = (uint32_t)__cvta_generic_to_shared(&S[stage].AH[0][0]);
            uint32_t aL = (uint32_t)__cvta_generic_to_shared(&S[stage].AL[0][0]);
            uint32_t bH = (uint32_t)__cvta_generic_to_shared(&S[stage].BH[0][0]);
            uint32_t bL = (uint32_t)__cvta_generic_to_shared(&S[stage].BL[0][0]);
            #pragma unroll
            for (int k16 = 0; k16 < 2; ++k16) {
                uint32_t bfH[2][4], bfL[2][4];
                #pragma unroll
                for (int hh = 0; hh < 2; ++hh) {
                    uint32_t boff = (uint32_t)((k16 * 16 + rowB) * (SB * 2)
                                               + warp_n * 64 + hh * 32 + colBq);
                    ldm_x4t(bfH[hh], bH + boff);
                    ldm_x4t(bfL[hh], bL + boff);
                }
                #pragma unroll
                for (int mt = 0; mt < 4; ++mt) {
                    uint32_t afH[4], afL[4];
                    uint32_t off = (uint32_t)((warp_m * 64 + mt * 16 + rowA) * (SA * 2)
                                              + k16 * 32 + kbA);
                    ldm_x4(afH, aH + off);
                    ldm_x4(afL, aL + off);
                    #pragma unroll
                    for (int nt = 0; nt < 4; ++nt)
                        mma16(acc[mt][nt], afH, bfH[nt >> 1] + (nt & 1) * 2);
                    #pragma unroll
                    for (int nt = 0; nt < 4; ++nt)
                        mma16(acc[mt][nt], afH, bfL[nt >> 1] + (nt & 1) * 2);
                    #pragma unroll
                    for (int nt = 0; nt < 4; ++nt)
                        mma16(acc[mt][nt], afL, bfH[nt >> 1] + (nt & 1) * 2);
                }
            }
        };

        const int NT = 33;
        fillA(0, 0); fillB(0, 0); cp_commit();
        fillA(1, 1); fillB(1, 1); cp_commit();
        for (int t = 0; t < NT; ++t) {
            if (t + 1 < NT) cp_wait1(); else cp_wait0();
            __syncthreads();
            if (t + 2 < NT) {
                int s2 = (t + 2) % 3;
                fillA(s2, t + 2); fillB(s2, t + 2); cp_commit();
            }
            compute(t % 3);
        }

        // gated activation epilogue -> g planes
        const float* bgp = d_bg + l * 1024 + mb * 128;
        int colbase = z * TT + t0 + warp_n * 32 + (lane & 3) * 2;
        #pragma unroll
        for (int mt = 0; mt < 4; ++mt) {
            int r  = warp_m * 64 + mt * 16 + (lane >> 2);
            int cc = gate_channel_of_row(r);
            int cg = mb * 64 + cc;
            float bs = bgp[r];
            float bt = bgp[r + 8];
            #pragma unroll
            for (int nt = 0; nt < 4; ++nt) {
                float s0  = acc[mt][nt][0] + bs;
                float s1  = acc[mt][nt][1] + bs;
                float tv0 = acc[mt][nt][2] + bt;
                float tv1 = acc[mt][nt][3] + bt;
                float g0 = __fdividef(1.f, 1.f + __expf(-s0)) *
                           (1.f - __fdividef(2.f, __expf(2.f * tv0) + 1.f));
                float g1 = __fdividef(1.f, 1.f + __expf(-s1)) *
                           (1.f - __fdividef(2.f, __expf(2.f * tv1) + 1.f));
                uint2 w = split2(g0, g1);
                size_t o = (size_t)cg * BT + colbase + nt * 8;
                *(uint32_t*)&d_gH[o] = w.x;
                *(uint32_t*)&d_gL[o] = w.y;
            }
        }

        // signal completion to skipres consumers of this (t0,z) group
        __threadfence();
        __syncthreads();
        if (tid == 0) atomicAdd(&d_cnt[z * 32 + tyb], 1);

    } else {
        // ================= SKIPRES tile =================
        int j   = bid - 512;
        int z   = j / 192;
        int r2_ = j % 192;
        int tyb = r2_ / 6;
        int mb  = r2_ % 6;
        int t0  = tyb * BN;

        // wait for the 8 gate tiles of this (t0,z) group
        if (tid == 0) {
            int tgt = 8 * (l + 1);
            while (ld_acq(&d_cnt[z * 32 + tyb]) < tgt) __nanosleep(64);
        }
        __syncthreads();

        float acc[4][4][4] = {};
        size_t aoff = ((size_t)l * 768 + mb * 128) * 512;

        auto fillA = [&](int stage, int tile) {
            int kt = tile * 32;
            #pragma unroll
            for (int p = 0; p < 4; ++p) {
                int idx = tid + p * 256;
                int pl  = idx >> 9;
                int rem = idx & 511;
                int row = rem >> 2;
                int kc  = rem & 3;
                const __nv_bfloat16* src = (pl ? d_WrsL : d_WrsH) + aoff
                                            + (size_t)row * 512 + kt + kc * 8;
                __nv_bfloat16* dst = pl ? &S[stage].AL[row][kc * 8] : &S[stage].AH[row][kc * 8];
                cp16(dst, src);
            }
        };
        auto fillB = [&](int stage, int tile) {
            int kt = tile * 32;
            #pragma unroll
            for (int p = 0; p < 4; ++p) {
                int idx = tid + p * 256;
                int pl  = idx >> 9;
                int rem = idx & 511;
                int row = rem >> 4;
                int c16 = rem & 15;
                const __nv_bfloat16* bp = pl ? d_gL : d_gH;
                const __nv_bfloat16* src = bp + (size_t)(kt + row) * BT + (size_t)z * TT
                                              + t0 + c16 * 8;
                __nv_bfloat16* dst = pl ? &S[stage].BL[row][c16 * 8] : &S[stage].BH[row][c16 * 8];
                cp16(dst, src);
            }
        };
        auto compute = [&](int stage) {
            uint32_t aH = (uint32_t)__cvta_generic_to_shared(&S[stage].AH[0][0]);
            uint32_t aL = (uint32_t)__cvta_generic_to_shared(&S[stage].AL[0][0]);
            uint32_t bH = (uint32_t)__cvta_generic_to_shared(&S[stage].BH[0][0]);
            uint32_t bL = (uint32_t)__cvta_generic_to_shared(&S[stage].BL[0][0]);
            #pragma unroll
            for (int k16 = 0; k16 < 2; ++k16) {
                uint32_t bfH[2][4], bfL[2][4];
                #pragma unroll
                for (int hh = 0; hh < 2; ++hh) {
                    uint32_t boff = (uint32_t)((k16 * 16 + rowB) * (SB * 2)
                                               + warp_n * 64 + hh * 32 + colBq);
                    ldm_x4t(bfH[hh], bH + boff);
                    ldm_x4t(bfL[hh], bL + boff);
                }
                #pragma unroll
                for (int mt = 0; mt < 4; ++mt) {
                    uint32_t afH[4], afL[4];
                    uint32_t off = (uint32_t)((warp_m * 64 + mt * 16 + rowA) * (SA * 2)
                                              + k16 * 32 + kbA);
                    ldm_x4(afH, aH + off);
                    ldm_x4(afL, aL + off);
                    #pragma unroll
                    for (int nt = 0; nt < 4; ++nt)
                        mma16(acc[mt][nt], afH, bfH[nt >> 1] + (nt & 1) * 2);
                    #pragma unroll
                    for (int nt = 0; nt < 4; ++nt)
                        mma16(acc[mt][nt], afH, bfL[nt >> 1] + (nt & 1) * 2);
                    #pragma unroll
                    for (int nt = 0; nt < 4; ++nt)
                        mma16(acc[mt][nt], afL, bfH[nt >> 1] + (nt & 1) * 2);
                }
            }
        };

        const int NT = 16;
        fillA(0, 0); fillB(0, 0); cp_commit();
        fillA(1, 1); fillB(1, 1); cp_commit();
        for (int t = 0; t < NT; ++t) {
            if (t + 1 < NT) cp_wait1(); else cp_wait0();
            __syncthreads();
            if (t + 2 < NT) {
                int s2 = (t + 2) % 3;
                fillA(s2, t + 2); fillB(s2, t + 2); cp_commit();
            }
            compute(t % 3);
        }

        __nv_bfloat16* resHw = d_resH + (size_t)wp * PLANE;
        __nv_bfloat16* resLw = d_resL + (size_t)wp * PLANE;
        __nv_bfloat16* s1Hw  = d_s1H  + (size_t)wp * PLANE;
        __nv_bfloat16* s1Lw  = d_s1L  + (size_t)wp * PLANE;

        int colbase = z * TT + t0 + warp_n * 32 + (lane & 3) * 2;
        #pragma unroll
        for (int mt = 0; mt < 4; ++mt) {
            int r0 = warp_m * 64 + mt * 16 + (lane >> 2);
            #pragma unroll
            for (int half = 0; half < 2; ++half) {
                int mg = mb * 128 + r0 + half * 8;
                float bias = d_brs[l * 768 + mg];
                #pragma unroll
                for (int nt = 0; nt < 4; ++nt) {
                    int col = colbase + nt * 8;
                    if (mg < 256) {
                        float* dst = &d_skip[(size_t)mg * BT + col];
                        float2 v = *(float2*)dst;
                        v.x += acc[mt][nt][half * 2 + 0] + bias;
                        v.y += acc[mt][nt][half * 2 + 1] + bias;
                        *(float2*)dst = v;
                    } else {
                        int ch = mg - 256;
                        float* dst = &d_res[(size_t)ch * BT + col];
                        float2 v = *(float2*)dst;
                        v.x += acc[mt][nt][half * 2 + 0] + bias;
                        v.y += acc[mt][nt][half * 2 + 1] + bias;
                        *(float2*)dst = v;
                        uint2 w = split2(v.x, v.y);
                        size_t o = (size_t)ch * BT + col;
                        *(uint32_t*)&resHw[o] = w.x;
                        *(uint32_t*)&resLw[o] = w.y;
                        if (dnext) {
                            int tl = col - z * TT;
                            if (tl + dnext < TT)     splitHL(v.x, s1Hw, s1Lw, o + dnext);
                            if (tl + 1 + dnext < TT) splitHL(v.y, s1Hw, s1Lw, o + 1 + dnext);
                            __nv_bfloat16 zb = __float2bfloat16_rn(0.f);
                            if (tl < dnext)     { s1Hw[o] = zb;     s1Lw[o] = zb; }
                            if (tl + 1 < dnext) { s1Hw[o + 1] = zb; s1Lw[o + 1] = zb; }
                        }
                    }
                }
            }
        }
    }
}

// =====================================================================
// Post GEMMs (register-split path): M=256, N=8192, K=256
// =====================================================================
struct PostTiles {
    uint2 A[2][16][132];
    uint2 B[2][16][68];
};
#define POST_SMEM ((int)sizeof(PostTiles))

__device__ __forceinline__ void post_sts(PostTiles& S, int buf, int tid,
                                         const uint4* ra, float4 rb0, float4 rb1) {
    #pragma unroll
    for (int p = 0; p < 4; ++p) {
        int e  = tid + p * 256;
        int k2 = e >> 6;
        int m2 = (e & 63) << 1;
        *(uint4*)&S.A[buf][k2][m2] = ra[p];
    }
    int k2 = tid >> 4;
    int n4 = (tid & 15) << 2;
    const float* x0 = &rb0.x;
    const float* x1 = &rb1.x;
    #pragma unroll
    for (int j = 0; j < 4; ++j)
        S.B[buf][k2][n4 + j] = split2(x0[j], x1[j]);
}

#define POST_MMA3(acc, Ab, Bb, wm, wn, lane_)                                   \
    do {                                                                        \
        int c_ = (lane_) & 3, q_ = (lane_) >> 2;                                \
        _Pragma("unroll")                                                       \
        for (int ksb = 0; ksb < 2; ++ksb) {                                     \
            uint2 bw[2][2];                                                     \
            _Pragma("unroll")                                                   \
            for (int nt = 0; nt < 2; ++nt) {                                    \
                bw[nt][0] = (Bb)[ksb * 8 + c_][(wn) * 16 + nt * 8 + q_];        \
                bw[nt][1] = (Bb)[ksb * 8 + c_ + 4][(wn) * 16 + nt * 8 + q_];    \
            }                                                                   \
            _Pragma("unroll")                                                   \
            for (int mt = 0; mt < 4; ++mt) {                                    \
                int r_ = (wm) * 64 + mt * 16 + q_;                              \
                uint2 a0 = (Ab)[ksb * 8 + c_][r_];                              \
                uint2 a1 = (Ab)[ksb * 8 + c_][r_ + 8];                          \
                uint2 a2 = (Ab)[ksb * 8 + c_ + 4][r_];                          \
                uint2 a3 = (Ab)[ksb * 8 + c_ + 4][r_ + 8];                      \
                uint32_t ah_[4] = {a0.x, a1.x, a2.x, a3.x};                     \
                uint32_t al_[4] = {a0.y, a1.y, a2.y, a3.y};                     \
                uint32_t bh0_[2] = {bw[0][0].x, bw[0][1].x};                    \
                uint32_t bh1_[2] = {bw[1][0].x, bw[1][1].x};                    \
                uint32_t bl0_[2] = {bw[0][0].y, bw[0][1].y};                    \
                uint32_t bl1_[2] = {bw[1][0].y, bw[1][1].y};                    \
                mma16(acc[mt][0], ah_, bh0_);                                   \
                mma16(acc[mt][1], ah_, bh1_);                                   \
                mma16(acc[mt][0], ah_, bl0_);                                   \
                mma16(acc[mt][1], ah_, bl1_);                                   \
                mma16(acc[mt][0], al_, bh0_);                                   \
                mma16(acc[mt][1], al_, bh1_);                                   \
            }                                                                   \
        }                                                                       \
    } while (0)

__global__ __launch_bounds__(256, 2)
void post_k(int mode, const float* __restrict__ bias, float* __restrict__ outp) {
    extern __shared__ uint8_t smraw[];
    PostTiles& S = *reinterpret_cast<PostTiles*>(smraw);

    int tid    = threadIdx.x;
    int lane   = tid & 31;
    int wid    = tid >> 5;
    int warp_m = wid & 1;
    int warp_n = wid >> 1;
    int mb     = blockIdx.x;
    int j0     = blockIdx.y * 64;

    const uint2* A    = (mode == 1) ? d_Wp12 : (mode == 2) ? d_Wp22 : d_Wp32;
    const float* Bsrc = (mode == 2) ? d_o1 : d_skip;

    float acc[4][2][4] = {};
    uint4  ra[4];
    float4 rb0, rb1;

    auto FETCH = [&](int tile) {
        #pragma unroll
        for (int p = 0; p < 4; ++p) {
            int e  = tid + p * 256;
            int k2 = e >> 6;
            int m2 = (e & 63) << 1;
            ra[p] = *(const uint4*)&A[(size_t)(tile * 16 + k2) * 256 + mb * 128 + m2];
        }
        int k2 = tid >> 4;
        int n4 = (tid & 15) << 2;
        int k0 = tile * 32 + 2 * k2;
        rb0 = *(const float4*)&Bsrc[(size_t)k0 * BT + j0 + n4];
        rb1 = *(const float4*)&Bsrc[(size_t)(k0 + 1) * BT + j0 + n4];
        if (mode == 1) {
            rb0.x = fmaxf(rb0.x, 0.f); rb0.y = fmaxf(rb0.y, 0.f);
            rb0.z = fmaxf(rb0.z, 0.f); rb0.w = fmaxf(rb0.w, 0.f);
            rb1.x = fmaxf(rb1.x, 0.f); rb1.y = fmaxf(rb1.y, 0.f);
            rb1.z = fmaxf(rb1.z, 0.f); rb1.w = fmaxf(rb1.w, 0.f);
        }
    };

    FETCH(0);
    post_sts(S, 0, tid, ra, rb0, rb1);
    __syncthreads();

    const int NT = 8;
    for (int t = 0; t < NT; ++t) {
        if (t + 1 < NT) FETCH(t + 1);
        POST_MMA3(acc, S.A[t & 1], S.B[t & 1], warp_m, warp_n, lane);
        if (t + 1 < NT) post_sts(S, (t + 1) & 1, tid, ra, rb0, rb1);
        __syncthreads();
    }

    int colbase = j0 + warp_n * 16 + (lane & 3) * 2;
    #pragma unroll
    for (int mt = 0; mt < 4; ++mt) {
        int r0 = warp_m * 64 + mt * 16 + (lane >> 2);
        #pragma unroll
        for (int half = 0; half < 2; ++half) {
            int mg = mb * 128 + r0 + half * 8;
            float bv = bias[mg];
            #pragma unroll
            for (int nt = 0; nt < 2; ++nt) {
                float v0 = acc[mt][nt][half * 2 + 0] + bv;
                float v1 = acc[mt][nt][half * 2 + 1] + bv;
                if (mode == 1) { v0 = fmaxf(v0, 0.f); v1 = fmaxf(v1, 0.f); }
                int col = colbase + nt * 8;
                if (mode == 3) {
                    outp[(size_t)(col    ) * NQ + mg] = v0;
                    outp[(size_t)(col + 1) * NQ + mg] = v1;
                } else {
                    float* dst = (mode == 1) ? &d_o1[(size_t)mg * BT + col]
                                             : &d_skip[(size_t)mg * BT + col];
                    *(float2*)dst = make_float2(v0, v1);
                }
            }
        }
    }
}

// =====================================================================
// Launch
// =====================================================================
extern "C" void kernel_launch(void* const* d_in, const int* in_sizes, int n_in,
                              void* d_out, int out_size) {
    const int*   x          = (const int*)  d_in[0];
    const float* h          = (const float*)d_in[1];
    const float* causal_w   = (const float*)d_in[2];
    const float* causal_b   = (const float*)d_in[3];
    const float* dil_sig_w  = (const float*)d_in[4];
    const float* dil_sig_b  = (const float*)d_in[5];
    const float* dil_tanh_w = (const float*)d_in[6];
    const float* dil_tanh_b = (const float*)d_in[7];
    const float* aux_sig_w  = (const float*)d_in[8];
    const float* aux_sig_b  = (const float*)d_in[9];
    const float* aux_tanh_w = (const float*)d_in[10];
    const float* aux_tanh_b = (const float*)d_in[11];
    const float* skip_w     = (const float*)d_in[12];
    const float* skip_b     = (const float*)d_in[13];
    const float* res_w      = (const float*)d_in[14];
    const float* res_b      = (const float*)d_in[15];
    const float* post1_w    = (const float*)d_in[16];
    const float* post1_b    = (const float*)d_in[17];
    const float* post2_w    = (const float*)d_in[18];
    const float* post2_b    = (const float*)d_in[19];
    const float* lin_w      = (const float*)d_in[20];
    const float* lin_b      = (const float*)d_in[21];

    cudaFuncSetAttribute(layer_k, cudaFuncAttributeMaxDynamicSharedMemorySize, GEMM_SMEM);
    cudaFuncSetAttribute(post_k,  cudaFuncAttributeMaxDynamicSharedMemorySize, POST_SMEM);

    {
        size_t n = PACK_TOTAL;
        pack_all_k<<<(unsigned)((n + 255) / 256), 256>>>(
            dil_sig_w, dil_tanh_w, aux_sig_w, aux_tanh_w, skip_w, res_w,
            dil_sig_b, dil_tanh_b, aux_sig_b, aux_tanh_b, skip_b, res_b,
            post1_w, post2_w, lin_w, h);
    }
    zero_skip_k<<<(NS * BT + 255) / 256, 256>>>();
    embed_k<<<dim3(BT / 256, NR), 256>>>(x, causal_w, causal_b);

    for (int l = 0; l < NLAYERS; ++l) {
        int d = 1 << (l % 10);
        int useS1 = (d < 8);
        int dn = (l + 1 < NLAYERS) ? (1 << ((l + 1) % 10)) : 0;
        if (dn >= 8) dn = 0;
        layer_k<<<896, NTHREADS, GEMM_SMEM>>>(l, d, useS1, dn);
    }

    post_k<<<dim3(2, BT / 64), 256, POST_SMEM>>>(1, post1_b, nullptr);
    post_k<<<dim3(2, BT / 64), 256, POST_SMEM>>>(2, post2_b, nullptr);
    post_k<<<dim3(2, BT / 64), 256, POST_SMEM>>>(3, lin_b, (float*)d_out);
}